// round 1
// baseline (speedup 1.0000x reference)
#include <cuda_runtime.h>
#include <math.h>

#define Dm   2048
#define Bb   2
#define Sseq 2048
#define Hh   16
#define DKk  128
#define Mrows 4096
#define SCALE 0.08838834764831844055f  // 1/sqrt(128)

__device__ float g_Q[Mrows * Dm];
__device__ float g_K[Mrows * Dm];
__device__ float g_V[Mrows * Dm];
__device__ float g_AO[Mrows * Dm];

// ---------------------------------------------------------------------------
// C[M,N] = A[M,K] * B[N,K]^T   (both operands K-major / row-major)
// 128x128 block, BK=16, 256 threads, 8x8 microtile, double-buffered smem.
// Grid: (N/128, M/128). All dims divisible (no guards needed).
// ---------------------------------------------------------------------------
__global__ __launch_bounds__(256, 2)
void sgemm_nt(const float* __restrict__ A, const float* __restrict__ Bw,
              float* __restrict__ C, int N, int K)
{
    __shared__ float As[2][16][132];
    __shared__ float Bs[2][16][132];

    const int tid = threadIdx.x;
    const int tx = tid & 15, ty = tid >> 4;
    const int bm = blockIdx.y * 128, bn = blockIdx.x * 128;
    const int m0 = tid >> 2;             // 0..63
    const int kq = (tid & 3) * 4;        // 0,4,8,12

    const float* Ap = A  + (size_t)(bm + m0) * K + kq;
    const float* Bp = Bw + (size_t)(bn + m0) * K + kq;

    float acc[8][8];
#pragma unroll
    for (int i = 0; i < 8; i++)
#pragma unroll
        for (int j = 0; j < 8; j++) acc[i][j] = 0.f;

    // prologue: tile 0 -> buffer 0
    {
        float4 a0 = *(const float4*)(Ap);
        float4 a1 = *(const float4*)(Ap + (size_t)64 * K);
        float4 b0 = *(const float4*)(Bp);
        float4 b1 = *(const float4*)(Bp + (size_t)64 * K);
        As[0][kq+0][m0] = a0.x; As[0][kq+1][m0] = a0.y; As[0][kq+2][m0] = a0.z; As[0][kq+3][m0] = a0.w;
        As[0][kq+0][m0+64] = a1.x; As[0][kq+1][m0+64] = a1.y; As[0][kq+2][m0+64] = a1.z; As[0][kq+3][m0+64] = a1.w;
        Bs[0][kq+0][m0] = b0.x; Bs[0][kq+1][m0] = b0.y; Bs[0][kq+2][m0] = b0.z; Bs[0][kq+3][m0] = b0.w;
        Bs[0][kq+0][m0+64] = b1.x; Bs[0][kq+1][m0+64] = b1.y; Bs[0][kq+2][m0+64] = b1.z; Bs[0][kq+3][m0+64] = b1.w;
    }
    __syncthreads();

    const int KT = K >> 4;
    int cur = 0;
    for (int kt = 0; kt < KT; ++kt) {
        float4 a0, a1, b0, b1;
        if (kt + 1 < KT) {
            const float* Ap2 = Ap + (kt + 1) * 16;
            const float* Bp2 = Bp + (kt + 1) * 16;
            a0 = *(const float4*)(Ap2);
            a1 = *(const float4*)(Ap2 + (size_t)64 * K);
            b0 = *(const float4*)(Bp2);
            b1 = *(const float4*)(Bp2 + (size_t)64 * K);
        }
#pragma unroll
        for (int k = 0; k < 16; ++k) {
            float4 ra0 = *(const float4*)&As[cur][k][ty*4];
            float4 ra1 = *(const float4*)&As[cur][k][64 + ty*4];
            float4 rb0 = *(const float4*)&Bs[cur][k][tx*4];
            float4 rb1 = *(const float4*)&Bs[cur][k][64 + tx*4];
            float av[8] = {ra0.x, ra0.y, ra0.z, ra0.w, ra1.x, ra1.y, ra1.z, ra1.w};
            float bv[8] = {rb0.x, rb0.y, rb0.z, rb0.w, rb1.x, rb1.y, rb1.z, rb1.w};
#pragma unroll
            for (int i = 0; i < 8; i++)
#pragma unroll
                for (int j = 0; j < 8; j++) acc[i][j] += av[i] * bv[j];
        }
        if (kt + 1 < KT) {
            int nxt = cur ^ 1;
            As[nxt][kq+0][m0] = a0.x; As[nxt][kq+1][m0] = a0.y; As[nxt][kq+2][m0] = a0.z; As[nxt][kq+3][m0] = a0.w;
            As[nxt][kq+0][m0+64] = a1.x; As[nxt][kq+1][m0+64] = a1.y; As[nxt][kq+2][m0+64] = a1.z; As[nxt][kq+3][m0+64] = a1.w;
            Bs[nxt][kq+0][m0] = b0.x; Bs[nxt][kq+1][m0] = b0.y; Bs[nxt][kq+2][m0] = b0.z; Bs[nxt][kq+3][m0] = b0.w;
            Bs[nxt][kq+0][m0+64] = b1.x; Bs[nxt][kq+1][m0+64] = b1.y; Bs[nxt][kq+2][m0+64] = b1.z; Bs[nxt][kq+3][m0+64] = b1.w;
            __syncthreads();
            cur = nxt;
        }
    }

#pragma unroll
    for (int i = 0; i < 8; i++) {
        int rm = bm + ((i < 4) ? (ty*4 + i) : (64 + ty*4 + (i - 4)));
        float4 v0 = make_float4(acc[i][0], acc[i][1], acc[i][2], acc[i][3]);
        float4 v1 = make_float4(acc[i][4], acc[i][5], acc[i][6], acc[i][7]);
        *(float4*)(C + (size_t)rm * N + bn + tx*4)      = v0;
        *(float4*)(C + (size_t)rm * N + bn + 64 + tx*4) = v1;
    }
}

// ---------------------------------------------------------------------------
// RoPE applied in-place to Q and K. One thread per (b,s,h,pair).
// inv_freq computed in fp64 then rounded to fp32 to match the reference's
// fp32 angle to <=1 ulp (angle = pos * inv_freq, pos up to 2047).
// ---------------------------------------------------------------------------
__global__ void rope_kernel(float* __restrict__ Qm, float* __restrict__ Km,
                            const int* __restrict__ pos)
{
    int idx = blockIdx.x * blockDim.x + threadIdx.x;  // grid sized exactly
    int i = idx & 63;
    int h = (idx >> 6) & 15;
    int s = (idx >> 10) & (Sseq - 1);
    int b = idx >> 21;

    float inv = (float)pow(10000.0, -(double)i / 64.0);
    float ang = (float)pos[s] * inv;
    float sn, cs;
    sincosf(ang, &sn, &cs);

    size_t off = ((size_t)(b * Sseq + s)) * Dm + h * DKk + 2 * i;
    float x1 = Qm[off], x2 = Qm[off + 1];
    Qm[off]     = x1 * cs - x2 * sn;
    Qm[off + 1] = x1 * sn + x2 * cs;
    x1 = Km[off]; x2 = Km[off + 1];
    Km[off]     = x1 * cs - x2 * sn;
    Km[off + 1] = x1 * sn + x2 * cs;
}

// ---------------------------------------------------------------------------
// Flash attention, fp32, causal. BQ=BKV=64, 256 threads (16x16 logical).
// smem: Qts[128][64] (d-major, pre-scaled), Kts[128][64], Vs[64][128],
//       Ss[64][65]. 114944 bytes dynamic -> 2 CTAs/SM.
// Each thread: 4 q-rows (ty) x 4 kv-cols (tx) for S; 4 rows x 8 d-cols for O.
// m/l kept in registers, replicated across the 16-lane tx group via shfl.
// ---------------------------------------------------------------------------
__global__ __launch_bounds__(256, 2)
void flash_attn(const float* __restrict__ Q, const float* __restrict__ K,
                const float* __restrict__ V, float* __restrict__ O)
{
    extern __shared__ float smem[];
    float* Qts = smem;            // 128*64
    float* Kts = smem + 8192;     // 128*64
    float* Vs  = smem + 16384;    // 64*128
    float* Ssm = smem + 24576;    // 64*65

    const int tid = threadIdx.x;
    const int tx = tid & 15, ty = tid >> 4;
    const int qt = gridDim.x - 1 - blockIdx.x;   // largest tiles first
    const int bh = blockIdx.y;
    const int b = bh >> 4, h = bh & 15;
    const int q0 = qt * 64;
    const size_t base = ((size_t)b * Sseq) * Dm + h * DKk;

    // Q -> smem transposed (d-major), pre-scaled by 1/sqrt(dk)
    for (int e = tid; e < 2048; e += 256) {
        int r = e & 63, c4 = e >> 6;
        const float4 v = *(const float4*)(Q + base + (size_t)(q0 + r) * Dm + c4 * 4);
        Qts[(c4*4+0)*64 + r] = v.x * SCALE;
        Qts[(c4*4+1)*64 + r] = v.y * SCALE;
        Qts[(c4*4+2)*64 + r] = v.z * SCALE;
        Qts[(c4*4+3)*64 + r] = v.w * SCALE;
    }

    float mrow[4], lrow[4], o[4][8];
#pragma unroll
    for (int i = 0; i < 4; i++) {
        mrow[i] = -1e30f; lrow[i] = 0.f;
#pragma unroll
        for (int k = 0; k < 8; k++) o[i][k] = 0.f;
    }

    const int ntiles = qt + 1;
    for (int j = 0; j < ntiles; ++j) {
        const int c0 = j * 64;
        for (int e = tid; e < 2048; e += 256) {           // K -> transposed
            int r = e & 63, c4 = e >> 6;
            const float4 v = *(const float4*)(K + base + (size_t)(c0 + r) * Dm + c4 * 4);
            Kts[(c4*4+0)*64 + r] = v.x;
            Kts[(c4*4+1)*64 + r] = v.y;
            Kts[(c4*4+2)*64 + r] = v.z;
            Kts[(c4*4+3)*64 + r] = v.w;
        }
        for (int e = tid; e < 2048; e += 256) {           // V -> natural
            int r = e >> 5, d4 = e & 31;
            *(float4*)(Vs + r * 128 + d4 * 4) =
                *(const float4*)(V + base + (size_t)(c0 + r) * Dm + d4 * 4);
        }
        __syncthreads();

        float s[4][4];
#pragma unroll
        for (int i = 0; i < 4; i++)
#pragma unroll
            for (int jj = 0; jj < 4; jj++) s[i][jj] = 0.f;

#pragma unroll 8
        for (int d = 0; d < 128; ++d) {
            float4 a  = *(const float4*)(Qts + d * 64 + ty * 4);
            float4 bv = *(const float4*)(Kts + d * 64 + tx * 4);
            s[0][0] += a.x*bv.x; s[0][1] += a.x*bv.y; s[0][2] += a.x*bv.z; s[0][3] += a.x*bv.w;
            s[1][0] += a.y*bv.x; s[1][1] += a.y*bv.y; s[1][2] += a.y*bv.z; s[1][3] += a.y*bv.w;
            s[2][0] += a.z*bv.x; s[2][1] += a.z*bv.y; s[2][2] += a.z*bv.z; s[2][3] += a.z*bv.w;
            s[3][0] += a.w*bv.x; s[3][1] += a.w*bv.y; s[3][2] += a.w*bv.z; s[3][3] += a.w*bv.w;
        }

        if (j == qt) {   // diagonal tile: causal mask (q0 == c0)
#pragma unroll
            for (int i = 0; i < 4; i++)
#pragma unroll
                for (int jj = 0; jj < 4; jj++)
                    if (tx*4 + jj > ty*4 + i) s[i][jj] = -1e30f;
        }

#pragma unroll
        for (int i = 0; i < 4; i++) {
            float mx = fmaxf(fmaxf(s[i][0], s[i][1]), fmaxf(s[i][2], s[i][3]));
            mx = fmaxf(mx, __shfl_xor_sync(0xffffffffu, mx, 8));
            mx = fmaxf(mx, __shfl_xor_sync(0xffffffffu, mx, 4));
            mx = fmaxf(mx, __shfl_xor_sync(0xffffffffu, mx, 2));
            mx = fmaxf(mx, __shfl_xor_sync(0xffffffffu, mx, 1));
            float mnew  = fmaxf(mrow[i], mx);
            float alpha = __expf(mrow[i] - mnew);
            mrow[i] = mnew;
            float p0 = __expf(s[i][0] - mnew);
            float p1 = __expf(s[i][1] - mnew);
            float p2 = __expf(s[i][2] - mnew);
            float p3 = __expf(s[i][3] - mnew);
            float rs = p0 + p1 + p2 + p3;
            rs += __shfl_xor_sync(0xffffffffu, rs, 8);
            rs += __shfl_xor_sync(0xffffffffu, rs, 4);
            rs += __shfl_xor_sync(0xffffffffu, rs, 2);
            rs += __shfl_xor_sync(0xffffffffu, rs, 1);
            lrow[i] = lrow[i] * alpha + rs;
#pragma unroll
            for (int k2 = 0; k2 < 8; k2++) o[i][k2] *= alpha;
            float* srow = Ssm + (ty*4 + i) * 65 + tx*4;
            srow[0] = p0; srow[1] = p1; srow[2] = p2; srow[3] = p3;
        }
        __syncwarp();   // Ss rows are produced & consumed within one warp

#pragma unroll 4
        for (int c = 0; c < 64; ++c) {
            float4 v0 = *(const float4*)(Vs + c * 128 + tx * 8);
            float4 v1 = *(const float4*)(Vs + c * 128 + tx * 8 + 4);
#pragma unroll
            for (int i = 0; i < 4; i++) {
                float p = Ssm[(ty*4 + i) * 65 + c];
                o[i][0] += p * v0.x; o[i][1] += p * v0.y;
                o[i][2] += p * v0.z; o[i][3] += p * v0.w;
                o[i][4] += p * v1.x; o[i][5] += p * v1.y;
                o[i][6] += p * v1.z; o[i][7] += p * v1.w;
            }
        }
        __syncthreads();  // protect Kts/Vs before next tile's loads
    }

#pragma unroll
    for (int i = 0; i < 4; i++) {
        float inv = 1.f / lrow[i];
        int r = q0 + ty*4 + i;
        float4 v0 = make_float4(o[i][0]*inv, o[i][1]*inv, o[i][2]*inv, o[i][3]*inv);
        float4 v1 = make_float4(o[i][4]*inv, o[i][5]*inv, o[i][6]*inv, o[i][7]*inv);
        *(float4*)(O + base + (size_t)r * Dm + tx * 8)     = v0;
        *(float4*)(O + base + (size_t)r * Dm + tx * 8 + 4) = v1;
    }
}

// ---------------------------------------------------------------------------
extern "C" void kernel_launch(void* const* d_in, const int* in_sizes, int n_in,
                              void* d_out, int out_size)
{
    const float* x  = (const float*)d_in[0];
    const float* WQ = (const float*)d_in[1];
    const float* WK = (const float*)d_in[2];
    const float* WV = (const float*)d_in[3];
    const float* WO = (const float*)d_in[4];
    const int*  pos = (const int*)d_in[5];
    float* out = (float*)d_out;

    float *Qp, *Kp, *Vp, *AOp;
    cudaGetSymbolAddress((void**)&Qp,  g_Q);
    cudaGetSymbolAddress((void**)&Kp,  g_K);
    cudaGetSymbolAddress((void**)&Vp,  g_V);
    cudaGetSymbolAddress((void**)&AOp, g_AO);

    dim3 gg(Dm / 128, Mrows / 128);   // (16, 32)
    sgemm_nt<<<gg, 256>>>(x, WQ, Qp, Dm, Dm);
    sgemm_nt<<<gg, 256>>>(x, WK, Kp, Dm, Dm);
    sgemm_nt<<<gg, 256>>>(x, WV, Vp, Dm, Dm);

    rope_kernel<<<(Bb * Sseq * Hh * (DKk / 2)) / 256, 256>>>(Qp, Kp, pos);

    cudaFuncSetAttribute(flash_attn, cudaFuncAttributeMaxDynamicSharedMemorySize, 114944);
    flash_attn<<<dim3(Sseq / 64, Bb * Hh), 256, 114944>>>(Qp, Kp, Vp, AOp);

    sgemm_nt<<<gg, 256>>>(AOp, WO, out, Dm, Dm);
}

// round 2
// speedup vs baseline: 1.1729x; 1.1729x over previous
#include <cuda_runtime.h>
#include <math.h>

#define Dm   2048
#define Bb   2
#define Sseq 2048
#define Hh   16
#define DKk  128
#define Mrows 4096
#define SCALE 0.08838834764831844055f  // 1/sqrt(128)

__device__ float g_Q[Mrows * Dm];
__device__ float g_K[Mrows * Dm];
__device__ float g_V[Mrows * Dm];
__device__ float g_AO[Mrows * Dm];
__device__ float g_invf[64];

// ---------------------------------------------------------------------------
// Tiny init: compute the 64 RoPE inverse frequencies once (fp64 pow, rounded
// to fp32 — bit-identical to the reference's fp32 inv_freq).
// ---------------------------------------------------------------------------
__global__ void init_freqs()
{
    int i = threadIdx.x;
    g_invf[i] = (float)pow(10000.0, -(double)i / 64.0);
}

// ---------------------------------------------------------------------------
// C[M,N] = A[M,K] * B[N,K]^T   (both operands K-major / row-major)
// 128x128 block, BK=16, 256 threads, 8x8 microtile, double-buffered smem.
// ---------------------------------------------------------------------------
__device__ __forceinline__
void sgemm_body(const float* __restrict__ A, const float* __restrict__ Bw,
                float* __restrict__ C, int N, int K)
{
    __shared__ float As[2][16][132];
    __shared__ float Bs[2][16][132];

    const int tid = threadIdx.x;
    const int tx = tid & 15, ty = tid >> 4;
    const int bm = blockIdx.y * 128, bn = blockIdx.x * 128;
    const int m0 = tid >> 2;             // 0..63
    const int kq = (tid & 3) * 4;        // 0,4,8,12

    const float* Ap = A  + (size_t)(bm + m0) * K + kq;
    const float* Bp = Bw + (size_t)(bn + m0) * K + kq;

    float acc[8][8];
#pragma unroll
    for (int i = 0; i < 8; i++)
#pragma unroll
        for (int j = 0; j < 8; j++) acc[i][j] = 0.f;

    {
        float4 a0 = *(const float4*)(Ap);
        float4 a1 = *(const float4*)(Ap + (size_t)64 * K);
        float4 b0 = *(const float4*)(Bp);
        float4 b1 = *(const float4*)(Bp + (size_t)64 * K);
        As[0][kq+0][m0] = a0.x; As[0][kq+1][m0] = a0.y; As[0][kq+2][m0] = a0.z; As[0][kq+3][m0] = a0.w;
        As[0][kq+0][m0+64] = a1.x; As[0][kq+1][m0+64] = a1.y; As[0][kq+2][m0+64] = a1.z; As[0][kq+3][m0+64] = a1.w;
        Bs[0][kq+0][m0] = b0.x; Bs[0][kq+1][m0] = b0.y; Bs[0][kq+2][m0] = b0.z; Bs[0][kq+3][m0] = b0.w;
        Bs[0][kq+0][m0+64] = b1.x; Bs[0][kq+1][m0+64] = b1.y; Bs[0][kq+2][m0+64] = b1.z; Bs[0][kq+3][m0+64] = b1.w;
    }
    __syncthreads();

    const int KT = K >> 4;
    int cur = 0;
    for (int kt = 0; kt < KT; ++kt) {
        float4 a0, a1, b0, b1;
        if (kt + 1 < KT) {
            const float* Ap2 = Ap + (kt + 1) * 16;
            const float* Bp2 = Bp + (kt + 1) * 16;
            a0 = *(const float4*)(Ap2);
            a1 = *(const float4*)(Ap2 + (size_t)64 * K);
            b0 = *(const float4*)(Bp2);
            b1 = *(const float4*)(Bp2 + (size_t)64 * K);
        }
#pragma unroll
        for (int k = 0; k < 16; ++k) {
            float4 ra0 = *(const float4*)&As[cur][k][ty*4];
            float4 ra1 = *(const float4*)&As[cur][k][64 + ty*4];
            float4 rb0 = *(const float4*)&Bs[cur][k][tx*4];
            float4 rb1 = *(const float4*)&Bs[cur][k][64 + tx*4];
            float av[8] = {ra0.x, ra0.y, ra0.z, ra0.w, ra1.x, ra1.y, ra1.z, ra1.w};
            float bv[8] = {rb0.x, rb0.y, rb0.z, rb0.w, rb1.x, rb1.y, rb1.z, rb1.w};
#pragma unroll
            for (int i = 0; i < 8; i++)
#pragma unroll
                for (int j = 0; j < 8; j++) acc[i][j] += av[i] * bv[j];
        }
        if (kt + 1 < KT) {
            int nxt = cur ^ 1;
            As[nxt][kq+0][m0] = a0.x; As[nxt][kq+1][m0] = a0.y; As[nxt][kq+2][m0] = a0.z; As[nxt][kq+3][m0] = a0.w;
            As[nxt][kq+0][m0+64] = a1.x; As[nxt][kq+1][m0+64] = a1.y; As[nxt][kq+2][m0+64] = a1.z; As[nxt][kq+3][m0+64] = a1.w;
            Bs[nxt][kq+0][m0] = b0.x; Bs[nxt][kq+1][m0] = b0.y; Bs[nxt][kq+2][m0] = b0.z; Bs[nxt][kq+3][m0] = b0.w;
            Bs[nxt][kq+0][m0+64] = b1.x; Bs[nxt][kq+1][m0+64] = b1.y; Bs[nxt][kq+2][m0+64] = b1.z; Bs[nxt][kq+3][m0+64] = b1.w;
            __syncthreads();
            cur = nxt;
        }
    }

#pragma unroll
    for (int i = 0; i < 8; i++) {
        int rm = bm + ((i < 4) ? (ty*4 + i) : (64 + ty*4 + (i - 4)));
        float4 v0 = make_float4(acc[i][0], acc[i][1], acc[i][2], acc[i][3]);
        float4 v1 = make_float4(acc[i][4], acc[i][5], acc[i][6], acc[i][7]);
        *(float4*)(C + (size_t)rm * N + bn + tx*4)      = v0;
        *(float4*)(C + (size_t)rm * N + bn + 64 + tx*4) = v1;
    }
}

__global__ __launch_bounds__(256, 2)
void sgemm_nt(const float* __restrict__ A, const float* __restrict__ Bw,
              float* __restrict__ C, int N, int K)
{
    sgemm_body(A, Bw, C, N, K);
}

// QKV fused: grid.z selects which weight/output. One launch, 3x the CTAs.
__global__ __launch_bounds__(256, 2)
void sgemm_qkv(const float* __restrict__ A,
               const float* __restrict__ WQ, const float* __restrict__ WK,
               const float* __restrict__ WV,
               float* __restrict__ Qo, float* __restrict__ Ko,
               float* __restrict__ Vo, int N, int K)
{
    const float* Bw = (blockIdx.z == 0) ? WQ : (blockIdx.z == 1) ? WK : WV;
    float*       C  = (blockIdx.z == 0) ? Qo : (blockIdx.z == 1) ? Ko : Vo;
    sgemm_body(A, Bw, C, N, K);
}

// ---------------------------------------------------------------------------
// RoPE applied in-place to Q and K. One thread per (b,s,h,pair).
// inv_freq read from precomputed table (fp64 pow hoisted to init_freqs).
// ---------------------------------------------------------------------------
__global__ __launch_bounds__(256)
void rope_kernel(float* __restrict__ Qm, float* __restrict__ Km,
                 const int* __restrict__ pos)
{
    int idx = blockIdx.x * blockDim.x + threadIdx.x;  // grid sized exactly
    int i = idx & 63;
    int h = (idx >> 6) & 15;
    int s = (idx >> 10) & (Sseq - 1);
    int b = idx >> 21;

    float ang = (float)pos[s] * g_invf[i];
    float sn, cs;
    sincosf(ang, &sn, &cs);

    size_t off = ((size_t)(b * Sseq + s)) * Dm + h * DKk + 2 * i;
    float2 q = *(float2*)(Qm + off);
    float2 k = *(float2*)(Km + off);
    *(float2*)(Qm + off) = make_float2(q.x * cs - q.y * sn, q.x * sn + q.y * cs);
    *(float2*)(Km + off) = make_float2(k.x * cs - k.y * sn, k.x * sn + k.y * cs);
}

// ---------------------------------------------------------------------------
// Flash attention, fp32, causal. BQ=BKV=64, 256 threads (16x16 logical).
// ---------------------------------------------------------------------------
__global__ __launch_bounds__(256, 2)
void flash_attn(const float* __restrict__ Q, const float* __restrict__ K,
                const float* __restrict__ V, float* __restrict__ O)
{
    extern __shared__ float smem[];
    float* Qts = smem;            // 128*64
    float* Kts = smem + 8192;     // 128*64
    float* Vs  = smem + 16384;    // 64*128
    float* Ssm = smem + 24576;    // 64*65

    const int tid = threadIdx.x;
    const int tx = tid & 15, ty = tid >> 4;
    const int qt = gridDim.x - 1 - blockIdx.x;   // largest tiles first
    const int bh = blockIdx.y;
    const int b = bh >> 4, h = bh & 15;
    const int q0 = qt * 64;
    const size_t base = ((size_t)b * Sseq) * Dm + h * DKk;

    for (int e = tid; e < 2048; e += 256) {
        int r = e & 63, c4 = e >> 6;
        const float4 v = *(const float4*)(Q + base + (size_t)(q0 + r) * Dm + c4 * 4);
        Qts[(c4*4+0)*64 + r] = v.x * SCALE;
        Qts[(c4*4+1)*64 + r] = v.y * SCALE;
        Qts[(c4*4+2)*64 + r] = v.z * SCALE;
        Qts[(c4*4+3)*64 + r] = v.w * SCALE;
    }

    float mrow[4], lrow[4], o[4][8];
#pragma unroll
    for (int i = 0; i < 4; i++) {
        mrow[i] = -1e30f; lrow[i] = 0.f;
#pragma unroll
        for (int k = 0; k < 8; k++) o[i][k] = 0.f;
    }

    const int ntiles = qt + 1;
    for (int j = 0; j < ntiles; ++j) {
        const int c0 = j * 64;
        for (int e = tid; e < 2048; e += 256) {           // K -> transposed
            int r = e & 63, c4 = e >> 6;
            const float4 v = *(const float4*)(K + base + (size_t)(c0 + r) * Dm + c4 * 4);
            Kts[(c4*4+0)*64 + r] = v.x;
            Kts[(c4*4+1)*64 + r] = v.y;
            Kts[(c4*4+2)*64 + r] = v.z;
            Kts[(c4*4+3)*64 + r] = v.w;
        }
        for (int e = tid; e < 2048; e += 256) {           // V -> natural
            int r = e >> 5, d4 = e & 31;
            *(float4*)(Vs + r * 128 + d4 * 4) =
                *(const float4*)(V + base + (size_t)(c0 + r) * Dm + d4 * 4);
        }
        __syncthreads();

        float s[4][4];
#pragma unroll
        for (int i = 0; i < 4; i++)
#pragma unroll
            for (int jj = 0; jj < 4; jj++) s[i][jj] = 0.f;

#pragma unroll 8
        for (int d = 0; d < 128; ++d) {
            float4 a  = *(const float4*)(Qts + d * 64 + ty * 4);
            float4 bv = *(const float4*)(Kts + d * 64 + tx * 4);
            s[0][0] += a.x*bv.x; s[0][1] += a.x*bv.y; s[0][2] += a.x*bv.z; s[0][3] += a.x*bv.w;
            s[1][0] += a.y*bv.x; s[1][1] += a.y*bv.y; s[1][2] += a.y*bv.z; s[1][3] += a.y*bv.w;
            s[2][0] += a.z*bv.x; s[2][1] += a.z*bv.y; s[2][2] += a.z*bv.z; s[2][3] += a.z*bv.w;
            s[3][0] += a.w*bv.x; s[3][1] += a.w*bv.y; s[3][2] += a.w*bv.z; s[3][3] += a.w*bv.w;
        }

        if (j == qt) {   // diagonal tile: causal mask (q0 == c0)
#pragma unroll
            for (int i = 0; i < 4; i++)
#pragma unroll
                for (int jj = 0; jj < 4; jj++)
                    if (tx*4 + jj > ty*4 + i) s[i][jj] = -1e30f;
        }

#pragma unroll
        for (int i = 0; i < 4; i++) {
            float mx = fmaxf(fmaxf(s[i][0], s[i][1]), fmaxf(s[i][2], s[i][3]));
            mx = fmaxf(mx, __shfl_xor_sync(0xffffffffu, mx, 8));
            mx = fmaxf(mx, __shfl_xor_sync(0xffffffffu, mx, 4));
            mx = fmaxf(mx, __shfl_xor_sync(0xffffffffu, mx, 2));
            mx = fmaxf(mx, __shfl_xor_sync(0xffffffffu, mx, 1));
            float mnew  = fmaxf(mrow[i], mx);
            float alpha = __expf(mrow[i] - mnew);
            mrow[i] = mnew;
            float p0 = __expf(s[i][0] - mnew);
            float p1 = __expf(s[i][1] - mnew);
            float p2 = __expf(s[i][2] - mnew);
            float p3 = __expf(s[i][3] - mnew);
            float rs = p0 + p1 + p2 + p3;
            rs += __shfl_xor_sync(0xffffffffu, rs, 8);
            rs += __shfl_xor_sync(0xffffffffu, rs, 4);
            rs += __shfl_xor_sync(0xffffffffu, rs, 2);
            rs += __shfl_xor_sync(0xffffffffu, rs, 1);
            lrow[i] = lrow[i] * alpha + rs;
#pragma unroll
            for (int k2 = 0; k2 < 8; k2++) o[i][k2] *= alpha;
            float* srow = Ssm + (ty*4 + i) * 65 + tx*4;
            srow[0] = p0; srow[1] = p1; srow[2] = p2; srow[3] = p3;
        }
        __syncwarp();   // Ss rows are produced & consumed within one warp

#pragma unroll 4
        for (int c = 0; c < 64; ++c) {
            float4 v0 = *(const float4*)(Vs + c * 128 + tx * 8);
            float4 v1 = *(const float4*)(Vs + c * 128 + tx * 8 + 4);
#pragma unroll
            for (int i = 0; i < 4; i++) {
                float p = Ssm[(ty*4 + i) * 65 + c];
                o[i][0] += p * v0.x; o[i][1] += p * v0.y;
                o[i][2] += p * v0.z; o[i][3] += p * v0.w;
                o[i][4] += p * v1.x; o[i][5] += p * v1.y;
                o[i][6] += p * v1.z; o[i][7] += p * v1.w;
            }
        }
        __syncthreads();  // protect Kts/Vs before next tile's loads
    }

#pragma unroll
    for (int i = 0; i < 4; i++) {
        float inv = 1.f / lrow[i];
        int r = q0 + ty*4 + i;
        float4 v0 = make_float4(o[i][0]*inv, o[i][1]*inv, o[i][2]*inv, o[i][3]*inv);
        float4 v1 = make_float4(o[i][4]*inv, o[i][5]*inv, o[i][6]*inv, o[i][7]*inv);
        *(float4*)(O + base + (size_t)r * Dm + tx * 8)     = v0;
        *(float4*)(O + base + (size_t)r * Dm + tx * 8 + 4) = v1;
    }
}

// ---------------------------------------------------------------------------
extern "C" void kernel_launch(void* const* d_in, const int* in_sizes, int n_in,
                              void* d_out, int out_size)
{
    const float* x  = (const float*)d_in[0];
    const float* WQ = (const float*)d_in[1];
    const float* WK = (const float*)d_in[2];
    const float* WV = (const float*)d_in[3];
    const float* WO = (const float*)d_in[4];
    const int*  pos = (const int*)d_in[5];
    float* out = (float*)d_out;

    float *Qp, *Kp, *Vp, *AOp;
    cudaGetSymbolAddress((void**)&Qp,  g_Q);
    cudaGetSymbolAddress((void**)&Kp,  g_K);
    cudaGetSymbolAddress((void**)&Vp,  g_V);
    cudaGetSymbolAddress((void**)&AOp, g_AO);

    init_freqs<<<1, 64>>>();

    dim3 gq(Dm / 128, Mrows / 128, 3);   // (16, 32, 3)
    sgemm_qkv<<<gq, 256>>>(x, WQ, WK, WV, Qp, Kp, Vp, Dm, Dm);

    rope_kernel<<<(Bb * Sseq * Hh * (DKk / 2)) / 256, 256>>>(Qp, Kp, pos);

    cudaFuncSetAttribute(flash_attn, cudaFuncAttributeMaxDynamicSharedMemorySize, 114944);
    flash_attn<<<dim3(Sseq / 64, Bb * Hh), 256, 114944>>>(Qp, Kp, Vp, AOp);

    dim3 gg(Dm / 128, Mrows / 128);      // (16, 32)
    sgemm_nt<<<gg, 256>>>(AOp, WO, out, Dm, Dm);
}

// round 4
// speedup vs baseline: 1.7436x; 1.4866x over previous
#include <cuda_runtime.h>
#include <cuda_bf16.h>
#include <math.h>
#include <cstdint>

#define Dm   2048
#define Bb   2
#define Sseq 2048
#define Hh   16
#define DKk  128
#define Mrows 4096
#define KP   6144          // 3 * 2048 (bf16x3 split packed along K)
#define KTILES (KP / 32)   // 192
#define SCALE 0.08838834764831844055f  // 1/sqrt(128)

__device__ float g_Q[Mrows * Dm];
__device__ float g_K[Mrows * Dm];
__device__ float g_V[Mrows * Dm];
__device__ float g_AO[Mrows * Dm];
__device__ float g_invf[64];

// bf16x3-split operands
__device__ __nv_bfloat16 g_Ax[(size_t)Mrows * KP];    // x'   [4096,6144]  [hi|hi|lo]
__device__ __nv_bfloat16 g_Aao[(size_t)Mrows * KP];   // AO'  [4096,6144]  [hi|hi|lo]
__device__ __nv_bfloat16 g_Wq[(size_t)Dm * KP];       // W'   [2048,6144]  [hi|lo|hi]
__device__ __nv_bfloat16 g_Wk[(size_t)Dm * KP];
__device__ __nv_bfloat16 g_Wv[(size_t)Dm * KP];
__device__ __nv_bfloat16 g_Wo[(size_t)Dm * KP];

__device__ __forceinline__ uint32_t smem_to_u32(const void* p) {
    uint32_t a;
    asm("{ .reg .u64 t; cvta.to.shared.u64 t, %1; cvt.u32.u64 %0, t; }"
        : "=r"(a) : "l"(p));
    return a;
}

// ===========================================================================
// init: RoPE inverse frequencies (fp64 pow once, rounded to fp32)
// ===========================================================================
__global__ void init_freqs()
{
    int i = threadIdx.x;
    g_invf[i] = (float)pow(10000.0, -(double)i / 64.0);
}

// ===========================================================================
// fp32 [R,2048] -> bf16x3-packed [R,6144].
//   A-operands: hi2_off=2048, lo_off=4096  => [hi|hi|lo]
//   W-operands: hi2_off=4096, lo_off=2048  => [hi|lo|hi]
// ===========================================================================
__global__ __launch_bounds__(256)
void convert_split(const float* __restrict__ X, __nv_bfloat16* __restrict__ Y,
                   int hi2_off, int lo_off)
{
    int idx = blockIdx.x * blockDim.x + threadIdx.x;
    int r  = idx >> 9;
    int c4 = idx & 511;
    float4 v = *(const float4*)(X + ((size_t)r << 11) + (c4 << 2));
    __nv_bfloat16 h0 = __float2bfloat16(v.x), h1 = __float2bfloat16(v.y);
    __nv_bfloat16 h2 = __float2bfloat16(v.z), h3 = __float2bfloat16(v.w);
    __nv_bfloat16 l0 = __float2bfloat16(v.x - __bfloat162float(h0));
    __nv_bfloat16 l1 = __float2bfloat16(v.y - __bfloat162float(h1));
    __nv_bfloat16 l2 = __float2bfloat16(v.z - __bfloat162float(h2));
    __nv_bfloat16 l3 = __float2bfloat16(v.w - __bfloat162float(h3));
    size_t row = (size_t)r * KP;
    __nv_bfloat162 hA = __nv_bfloat162(h0, h1), hB = __nv_bfloat162(h2, h3);
    __nv_bfloat162 lA = __nv_bfloat162(l0, l1), lB = __nv_bfloat162(l2, l3);
    __nv_bfloat162* p0 = (__nv_bfloat162*)(Y + row + (c4 << 2));
    __nv_bfloat162* p1 = (__nv_bfloat162*)(Y + row + hi2_off + (c4 << 2));
    __nv_bfloat162* p2 = (__nv_bfloat162*)(Y + row + lo_off + (c4 << 2));
    p0[0] = hA; p0[1] = hB;
    p1[0] = hA; p1[1] = hB;
    p2[0] = lA; p2[1] = lB;
}

// ===========================================================================
// bf16 mma.sync GEMM: C[M,2048] = A'[M,6144] * B'[N,6144]^T (K-major both).
// CTA 128x128, BK=32, 4-stage cp.async pipeline, 8 warps (2x4), warp 64x32,
// ldmatrix.x4 fragments, m16n8k16 bf16 MMA, fp32 accum.
// smem: per-stage A[128][40]bf16 (80B pitch) + B same = 20480 B; 4 stages.
// ===========================================================================
#define STG_OP 10240u    // bytes per operand per stage

__device__ __forceinline__
void gemm_mma_body(const __nv_bfloat16* __restrict__ A,
                   const __nv_bfloat16* __restrict__ B,
                   float* __restrict__ C)
{
    extern __shared__ __align__(128) char gsm[];
    const uint32_t sbase = smem_to_u32(gsm);
    const int tid = threadIdx.x;
    const int lane = tid & 31, wid = tid >> 5;
    const int bm = blockIdx.y * 128, bn = blockIdx.x * 128;
    const int wm = (wid >> 2) * 64, wn = (wid & 3) * 32;

    const __nv_bfloat16* Ag = A + (size_t)bm * KP;
    const __nv_bfloat16* Bg = B + (size_t)bn * KP;

    const uint32_t sA0 = sbase;
    const uint32_t sB0 = sbase + 4 * STG_OP;

    float c[4][4][4];
#pragma unroll
    for (int i = 0; i < 4; i++)
#pragma unroll
        for (int j = 0; j < 4; j++)
#pragma unroll
            for (int k = 0; k < 4; k++) c[i][j][k] = 0.f;

    // per-thread chunk coords for fills: 512 16B-chunks per operand
    const int frow0 = tid >> 2, fseg = tid & 3;          // chunk tid
    const int frow1 = (tid + 256) >> 2;                  // chunk tid+256

#define GFILL(s) do {                                                         \
        int _buf = (s) & 3;                                                   \
        uint32_t _sa = sA0 + _buf * STG_OP;                                   \
        uint32_t _sb = sB0 + _buf * STG_OP;                                   \
        int _ks = (s) * 32;                                                   \
        uint32_t _d0 = (uint32_t)(frow0 * 80 + fseg * 16);                    \
        uint32_t _d1 = (uint32_t)(frow1 * 80 + fseg * 16);                    \
        const void* _ga0 = Ag + (size_t)frow0 * KP + _ks + fseg * 8;          \
        const void* _gb0 = Bg + (size_t)frow0 * KP + _ks + fseg * 8;          \
        const void* _ga1 = Ag + (size_t)frow1 * KP + _ks + fseg * 8;          \
        const void* _gb1 = Bg + (size_t)frow1 * KP + _ks + fseg * 8;          \
        asm volatile("cp.async.cg.shared.global [%0], [%1], 16;" :: "r"(_sa + _d0), "l"(_ga0) : "memory"); \
        asm volatile("cp.async.cg.shared.global [%0], [%1], 16;" :: "r"(_sb + _d0), "l"(_gb0) : "memory"); \
        asm volatile("cp.async.cg.shared.global [%0], [%1], 16;" :: "r"(_sa + _d1), "l"(_ga1) : "memory"); \
        asm volatile("cp.async.cg.shared.global [%0], [%1], 16;" :: "r"(_sb + _d1), "l"(_gb1) : "memory"); \
        asm volatile("cp.async.commit_group;" ::: "memory");                  \
    } while (0)

    GFILL(0); GFILL(1); GFILL(2);

    const uint32_t aRowOff = (uint32_t)((wm + (lane & 15)) * 80);
    const uint32_t bRowOff = (uint32_t)((wn + (lane & 7) + ((lane >> 4) << 3)) * 80);
    const uint32_t aColOff = (uint32_t)((lane >> 4) << 4);
    const uint32_t bColOff = (uint32_t)(((lane >> 3) & 1) << 4);

    for (int kt = 0; kt < KTILES; kt++) {
        asm volatile("cp.async.wait_group 2;" ::: "memory");
        __syncthreads();
        if (kt + 3 < KTILES) { GFILL(kt + 3); }
        else { asm volatile("cp.async.commit_group;" ::: "memory"); }

        const int buf = kt & 3;
        const uint32_t sa = sA0 + buf * STG_OP;
        const uint32_t sb = sB0 + buf * STG_OP;

#pragma unroll
        for (int ks = 0; ks < 2; ks++) {
            uint32_t a[4][4], bf[2][4];
            const uint32_t ac = ks * 32 + aColOff;
            const uint32_t bc = ks * 32 + bColOff;
#pragma unroll
            for (int mt = 0; mt < 4; mt++) {
                uint32_t ad = sa + aRowOff + (uint32_t)(mt * 16 * 80) + ac;
                asm volatile("ldmatrix.sync.aligned.m8n8.x4.shared.b16 {%0,%1,%2,%3}, [%4];"
                    : "=r"(a[mt][0]), "=r"(a[mt][1]), "=r"(a[mt][2]), "=r"(a[mt][3]) : "r"(ad));
            }
#pragma unroll
            for (int nt2 = 0; nt2 < 2; nt2++) {
                uint32_t bd = sb + bRowOff + (uint32_t)(nt2 * 16 * 80) + bc;
                asm volatile("ldmatrix.sync.aligned.m8n8.x4.shared.b16 {%0,%1,%2,%3}, [%4];"
                    : "=r"(bf[nt2][0]), "=r"(bf[nt2][1]), "=r"(bf[nt2][2]), "=r"(bf[nt2][3]) : "r"(bd));
            }
#pragma unroll
            for (int mt = 0; mt < 4; mt++)
#pragma unroll
                for (int nt = 0; nt < 4; nt++) {
                    asm volatile("mma.sync.aligned.m16n8k16.row.col.f32.bf16.bf16.f32 "
                        "{%0,%1,%2,%3}, {%4,%5,%6,%7}, {%8,%9}, {%0,%1,%2,%3};"
                        : "+f"(c[mt][nt][0]), "+f"(c[mt][nt][1]),
                          "+f"(c[mt][nt][2]), "+f"(c[mt][nt][3])
                        : "r"(a[mt][0]), "r"(a[mt][1]), "r"(a[mt][2]), "r"(a[mt][3]),
                          "r"(bf[nt >> 1][(nt & 1) * 2]), "r"(bf[nt >> 1][(nt & 1) * 2 + 1]));
                }
        }
    }
#undef GFILL

    const int r0 = bm + wm + (lane >> 2);
    const int c0 = bn + wn + (lane & 3) * 2;
#pragma unroll
    for (int mt = 0; mt < 4; mt++)
#pragma unroll
        for (int nt = 0; nt < 4; nt++) {
            int rr = r0 + mt * 16, cc = c0 + nt * 8;
            *(float2*)(C + (size_t)rr * Dm + cc)       = make_float2(c[mt][nt][0], c[mt][nt][1]);
            *(float2*)(C + (size_t)(rr + 8) * Dm + cc) = make_float2(c[mt][nt][2], c[mt][nt][3]);
        }
}

__global__ __launch_bounds__(256)
void gemm_bf3(const __nv_bfloat16* __restrict__ A, const __nv_bfloat16* __restrict__ B,
              float* __restrict__ C)
{
    gemm_mma_body(A, B, C);
}

__global__ __launch_bounds__(256)
void gemm_bf3_qkv(const __nv_bfloat16* __restrict__ A,
                  const __nv_bfloat16* __restrict__ WQ, const __nv_bfloat16* __restrict__ WK,
                  const __nv_bfloat16* __restrict__ WV,
                  float* __restrict__ Qo, float* __restrict__ Ko, float* __restrict__ Vo)
{
    const __nv_bfloat16* Bw = (blockIdx.z == 0) ? WQ : (blockIdx.z == 1) ? WK : WV;
    float*               C  = (blockIdx.z == 0) ? Qo : (blockIdx.z == 1) ? Ko : Vo;
    gemm_mma_body(A, Bw, C);
}

// ===========================================================================
// RoPE in-place on fp32 Q and K
// ===========================================================================
__global__ __launch_bounds__(256)
void rope_kernel(float* __restrict__ Qm, float* __restrict__ Km,
                 const int* __restrict__ pos)
{
    int idx = blockIdx.x * blockDim.x + threadIdx.x;
    int i = idx & 63;
    int h = (idx >> 6) & 15;
    int s = (idx >> 10) & (Sseq - 1);
    int b = idx >> 21;

    float ang = (float)pos[s] * g_invf[i];
    float sn, cs;
    sincosf(ang, &sn, &cs);

    size_t off = ((size_t)(b * Sseq + s)) * Dm + h * DKk + 2 * i;
    float2 q = *(float2*)(Qm + off);
    float2 k = *(float2*)(Km + off);
    *(float2*)(Qm + off) = make_float2(q.x * cs - q.y * sn, q.x * sn + q.y * cs);
    *(float2*)(Km + off) = make_float2(k.x * cs - k.y * sn, k.x * sn + k.y * cs);
}

// ===========================================================================
// Flash attention, fp32, causal (unchanged; known-good)
// ===========================================================================
__global__ __launch_bounds__(256, 2)
void flash_attn(const float* __restrict__ Q, const float* __restrict__ K,
                const float* __restrict__ V, float* __restrict__ O)
{
    extern __shared__ float smem[];
    float* Qts = smem;            // 128*64
    float* Kts = smem + 8192;     // 128*64
    float* Vs  = smem + 16384;    // 64*128
    float* Ssm = smem + 24576;    // 64*65

    const int tid = threadIdx.x;
    const int tx = tid & 15, ty = tid >> 4;
    const int qt = gridDim.x - 1 - blockIdx.x;
    const int bh = blockIdx.y;
    const int b = bh >> 4, h = bh & 15;
    const int q0 = qt * 64;
    const size_t base = ((size_t)b * Sseq) * Dm + h * DKk;

    for (int e = tid; e < 2048; e += 256) {
        int r = e & 63, c4 = e >> 6;
        const float4 v = *(const float4*)(Q + base + (size_t)(q0 + r) * Dm + c4 * 4);
        Qts[(c4*4+0)*64 + r] = v.x * SCALE;
        Qts[(c4*4+1)*64 + r] = v.y * SCALE;
        Qts[(c4*4+2)*64 + r] = v.z * SCALE;
        Qts[(c4*4+3)*64 + r] = v.w * SCALE;
    }

    float mrow[4], lrow[4], o[4][8];
#pragma unroll
    for (int i = 0; i < 4; i++) {
        mrow[i] = -1e30f; lrow[i] = 0.f;
#pragma unroll
        for (int k = 0; k < 8; k++) o[i][k] = 0.f;
    }

    const int ntiles = qt + 1;
    for (int j = 0; j < ntiles; ++j) {
        const int c0 = j * 64;
        for (int e = tid; e < 2048; e += 256) {
            int r = e & 63, c4 = e >> 6;
            const float4 v = *(const float4*)(K + base + (size_t)(c0 + r) * Dm + c4 * 4);
            Kts[(c4*4+0)*64 + r] = v.x;
            Kts[(c4*4+1)*64 + r] = v.y;
            Kts[(c4*4+2)*64 + r] = v.z;
            Kts[(c4*4+3)*64 + r] = v.w;
        }
        for (int e = tid; e < 2048; e += 256) {
            int r = e >> 5, d4 = e & 31;
            *(float4*)(Vs + r * 128 + d4 * 4) =
                *(const float4*)(V + base + (size_t)(c0 + r) * Dm + d4 * 4);
        }
        __syncthreads();

        float s[4][4];
#pragma unroll
        for (int i = 0; i < 4; i++)
#pragma unroll
            for (int jj = 0; jj < 4; jj++) s[i][jj] = 0.f;

#pragma unroll 8
        for (int d = 0; d < 128; ++d) {
            float4 a  = *(const float4*)(Qts + d * 64 + ty * 4);
            float4 bv = *(const float4*)(Kts + d * 64 + tx * 4);
            s[0][0] += a.x*bv.x; s[0][1] += a.x*bv.y; s[0][2] += a.x*bv.z; s[0][3] += a.x*bv.w;
            s[1][0] += a.y*bv.x; s[1][1] += a.y*bv.y; s[1][2] += a.y*bv.z; s[1][3] += a.y*bv.w;
            s[2][0] += a.z*bv.x; s[2][1] += a.z*bv.y; s[2][2] += a.z*bv.z; s[2][3] += a.z*bv.w;
            s[3][0] += a.w*bv.x; s[3][1] += a.w*bv.y; s[3][2] += a.w*bv.z; s[3][3] += a.w*bv.w;
        }

        if (j == qt) {
#pragma unroll
            for (int i = 0; i < 4; i++)
#pragma unroll
                for (int jj = 0; jj < 4; jj++)
                    if (tx*4 + jj > ty*4 + i) s[i][jj] = -1e30f;
        }

#pragma unroll
        for (int i = 0; i < 4; i++) {
            float mx = fmaxf(fmaxf(s[i][0], s[i][1]), fmaxf(s[i][2], s[i][3]));
            mx = fmaxf(mx, __shfl_xor_sync(0xffffffffu, mx, 8));
            mx = fmaxf(mx, __shfl_xor_sync(0xffffffffu, mx, 4));
            mx = fmaxf(mx, __shfl_xor_sync(0xffffffffu, mx, 2));
            mx = fmaxf(mx, __shfl_xor_sync(0xffffffffu, mx, 1));
            float mnew  = fmaxf(mrow[i], mx);
            float alpha = __expf(mrow[i] - mnew);
            mrow[i] = mnew;
            float p0 = __expf(s[i][0] - mnew);
            float p1 = __expf(s[i][1] - mnew);
            float p2 = __expf(s[i][2] - mnew);
            float p3 = __expf(s[i][3] - mnew);
            float rs = p0 + p1 + p2 + p3;
            rs += __shfl_xor_sync(0xffffffffu, rs, 8);
            rs += __shfl_xor_sync(0xffffffffu, rs, 4);
            rs += __shfl_xor_sync(0xffffffffu, rs, 2);
            rs += __shfl_xor_sync(0xffffffffu, rs, 1);
            lrow[i] = lrow[i] * alpha + rs;
#pragma unroll
            for (int k2 = 0; k2 < 8; k2++) o[i][k2] *= alpha;
            float* srow = Ssm + (ty*4 + i) * 65 + tx*4;
            srow[0] = p0; srow[1] = p1; srow[2] = p2; srow[3] = p3;
        }
        __syncwarp();

#pragma unroll 4
        for (int c = 0; c < 64; ++c) {
            float4 v0 = *(const float4*)(Vs + c * 128 + tx * 8);
            float4 v1 = *(const float4*)(Vs + c * 128 + tx * 8 + 4);
#pragma unroll
            for (int i = 0; i < 4; i++) {
                float p = Ssm[(ty*4 + i) * 65 + c];
                o[i][0] += p * v0.x; o[i][1] += p * v0.y;
                o[i][2] += p * v0.z; o[i][3] += p * v0.w;
                o[i][4] += p * v1.x; o[i][5] += p * v1.y;
                o[i][6] += p * v1.z; o[i][7] += p * v1.w;
            }
        }
        __syncthreads();
    }

#pragma unroll
    for (int i = 0; i < 4; i++) {
        float inv = 1.f / lrow[i];
        int r = q0 + ty*4 + i;
        float4 v0 = make_float4(o[i][0]*inv, o[i][1]*inv, o[i][2]*inv, o[i][3]*inv);
        float4 v1 = make_float4(o[i][4]*inv, o[i][5]*inv, o[i][6]*inv, o[i][7]*inv);
        *(float4*)(O + base + (size_t)r * Dm + tx * 8)     = v0;
        *(float4*)(O + base + (size_t)r * Dm + tx * 8 + 4) = v1;
    }
}

// ===========================================================================
extern "C" void kernel_launch(void* const* d_in, const int* in_sizes, int n_in,
                              void* d_out, int out_size)
{
    const float* x  = (const float*)d_in[0];
    const float* WQ = (const float*)d_in[1];
    const float* WK = (const float*)d_in[2];
    const float* WV = (const float*)d_in[3];
    const float* WO = (const float*)d_in[4];
    const int*  pos = (const int*)d_in[5];
    float* out = (float*)d_out;

    float *Qp, *Kp, *Vp, *AOp;
    __nv_bfloat16 *Axp, *Aaop, *Wqp, *Wkp, *Wvp, *Wop;
    cudaGetSymbolAddress((void**)&Qp,  g_Q);
    cudaGetSymbolAddress((void**)&Kp,  g_K);
    cudaGetSymbolAddress((void**)&Vp,  g_V);
    cudaGetSymbolAddress((void**)&AOp, g_AO);
    cudaGetSymbolAddress((void**)&Axp, g_Ax);
    cudaGetSymbolAddress((void**)&Aaop, g_Aao);
    cudaGetSymbolAddress((void**)&Wqp, g_Wq);
    cudaGetSymbolAddress((void**)&Wkp, g_Wk);
    cudaGetSymbolAddress((void**)&Wvp, g_Wv);
    cudaGetSymbolAddress((void**)&Wop, g_Wo);

    init_freqs<<<1, 64>>>();

    convert_split<<<(Mrows * Dm / 4) / 256, 256>>>(x,  Axp, 2048, 4096);
    convert_split<<<(Dm * Dm / 4) / 256, 256>>>(WQ, Wqp, 4096, 2048);
    convert_split<<<(Dm * Dm / 4) / 256, 256>>>(WK, Wkp, 4096, 2048);
    convert_split<<<(Dm * Dm / 4) / 256, 256>>>(WV, Wvp, 4096, 2048);
    convert_split<<<(Dm * Dm / 4) / 256, 256>>>(WO, Wop, 4096, 2048);

    cudaFuncSetAttribute(gemm_bf3_qkv, cudaFuncAttributeMaxDynamicSharedMemorySize, 81920);
    cudaFuncSetAttribute(gemm_bf3,     cudaFuncAttributeMaxDynamicSharedMemorySize, 81920);

    gemm_bf3_qkv<<<dim3(Dm / 128, Mrows / 128, 3), 256, 81920>>>(Axp, Wqp, Wkp, Wvp, Qp, Kp, Vp);

    rope_kernel<<<(Bb * Sseq * Hh * (DKk / 2)) / 256, 256>>>(Qp, Kp, pos);

    cudaFuncSetAttribute(flash_attn, cudaFuncAttributeMaxDynamicSharedMemorySize, 114944);
    flash_attn<<<dim3(Sseq / 64, Bb * Hh), 256, 114944>>>(Qp, Kp, Vp, AOp);

    convert_split<<<(Mrows * Dm / 4) / 256, 256>>>(AOp, Aaop, 2048, 4096);
    gemm_bf3<<<dim3(Dm / 128, Mrows / 128), 256, 81920>>>(Aaop, Wop, out);
}

// round 5
// speedup vs baseline: 2.7834x; 1.5963x over previous
#include <cuda_runtime.h>
#include <cuda_bf16.h>
#include <math.h>
#include <cstdint>

#define Dm   2048
#define Bb   2
#define Sseq 2048
#define Hh   16
#define DKk  128
#define Mrows 4096
#define KP   6144          // 3 * 2048 (bf16x3 split packed along K)
#define KTILES (KP / 32)   // 192
#define SCALE 0.08838834764831844055f  // 1/sqrt(128)

__device__ float g_Q[Mrows * Dm];
__device__ float g_K[Mrows * Dm];
__device__ float g_V[Mrows * Dm];
__device__ float g_AO[Mrows * Dm];
__device__ float g_invf[64];

// bf16x3-split GEMM operands
__device__ __nv_bfloat16 g_Ax[(size_t)Mrows * KP];    // [hi|hi|lo]
__device__ __nv_bfloat16 g_Aao[(size_t)Mrows * KP];   // [hi|hi|lo]
__device__ __nv_bfloat16 g_Wq[(size_t)Dm * KP];       // [hi|lo|hi]
__device__ __nv_bfloat16 g_Wk[(size_t)Dm * KP];
__device__ __nv_bfloat16 g_Wv[(size_t)Dm * KP];
__device__ __nv_bfloat16 g_Wo[(size_t)Dm * KP];

// per-head split Q/K/V for flash:  [bh][s][128] bf16
#define HS ((size_t)32 * 2048 * 128)
__device__ __nv_bfloat16 g_Qh[HS];
__device__ __nv_bfloat16 g_Ql[HS];
__device__ __nv_bfloat16 g_Kh[HS];
__device__ __nv_bfloat16 g_Kl[HS];
__device__ __nv_bfloat16 g_Vh[HS];
__device__ __nv_bfloat16 g_Vl[HS];

__device__ __forceinline__ uint32_t smem_to_u32(const void* p) {
    uint32_t a;
    asm("{ .reg .u64 t; cvta.to.shared.u64 t, %1; cvt.u32.u64 %0, t; }"
        : "=r"(a) : "l"(p));
    return a;
}
__device__ __forceinline__ void cpa16(uint32_t d, const void* g) {
    asm volatile("cp.async.cg.shared.global [%0], [%1], 16;" :: "r"(d), "l"(g) : "memory");
}
// pack two fp32 -> bf16x2 register {low: lo, high: hi}
__device__ __forceinline__ uint32_t pack_bf16x2(float lo, float hi) {
    uint32_t r;
    asm("cvt.rn.bf16x2.f32 %0, %1, %2;" : "=r"(r) : "f"(hi), "f"(lo));
    return r;
}
__device__ __forceinline__ float bf16rt(float x) {   // round-trip through bf16
    return __bfloat162float(__float2bfloat16(x));
}

#define LDSM4(R, addr) \
    asm volatile("ldmatrix.sync.aligned.m8n8.x4.shared.b16 {%0,%1,%2,%3}, [%4];" \
        : "=r"((R)[0]), "=r"((R)[1]), "=r"((R)[2]), "=r"((R)[3]) : "r"(addr))
#define LDSM4T(R, addr) \
    asm volatile("ldmatrix.sync.aligned.m8n8.x4.trans.shared.b16 {%0,%1,%2,%3}, [%4];" \
        : "=r"((R)[0]), "=r"((R)[1]), "=r"((R)[2]), "=r"((R)[3]) : "r"(addr))
#define MMA16816(C, A, B0, B1) \
    asm volatile("mma.sync.aligned.m16n8k16.row.col.f32.bf16.bf16.f32 " \
        "{%0,%1,%2,%3}, {%4,%5,%6,%7}, {%8,%9}, {%0,%1,%2,%3};" \
        : "+f"((C)[0]), "+f"((C)[1]), "+f"((C)[2]), "+f"((C)[3]) \
        : "r"((A)[0]), "r"((A)[1]), "r"((A)[2]), "r"((A)[3]), "r"(B0), "r"(B1))

// ===========================================================================
__global__ void init_freqs()
{
    int i = threadIdx.x;
    g_invf[i] = (float)pow(10000.0, -(double)i / 64.0);
}

// ===========================================================================
// fp32 [R,2048] -> bf16x3-packed [R,6144] (GEMM operands)
// ===========================================================================
__global__ __launch_bounds__(256)
void convert_split(const float* __restrict__ X, __nv_bfloat16* __restrict__ Y,
                   int hi2_off, int lo_off)
{
    int idx = blockIdx.x * blockDim.x + threadIdx.x;
    int r  = idx >> 9;
    int c4 = idx & 511;
    float4 v = *(const float4*)(X + ((size_t)r << 11) + (c4 << 2));
    __nv_bfloat16 h0 = __float2bfloat16(v.x), h1 = __float2bfloat16(v.y);
    __nv_bfloat16 h2 = __float2bfloat16(v.z), h3 = __float2bfloat16(v.w);
    __nv_bfloat16 l0 = __float2bfloat16(v.x - __bfloat162float(h0));
    __nv_bfloat16 l1 = __float2bfloat16(v.y - __bfloat162float(h1));
    __nv_bfloat16 l2 = __float2bfloat16(v.z - __bfloat162float(h2));
    __nv_bfloat16 l3 = __float2bfloat16(v.w - __bfloat162float(h3));
    size_t row = (size_t)r * KP;
    __nv_bfloat162 hA = __nv_bfloat162(h0, h1), hB = __nv_bfloat162(h2, h3);
    __nv_bfloat162 lA = __nv_bfloat162(l0, l1), lB = __nv_bfloat162(l2, l3);
    __nv_bfloat162* p0 = (__nv_bfloat162*)(Y + row + (c4 << 2));
    __nv_bfloat162* p1 = (__nv_bfloat162*)(Y + row + hi2_off + (c4 << 2));
    __nv_bfloat162* p2 = (__nv_bfloat162*)(Y + row + lo_off + (c4 << 2));
    p0[0] = hA; p0[1] = hB;
    p1[0] = hA; p1[1] = hB;
    p2[0] = lA; p2[1] = lB;
}

// ===========================================================================
// Split rope'd Q (pre-scaled), K, V into per-head [bh][s][128] bf16 hi/lo.
// One float4 per thread per tensor.
// ===========================================================================
__global__ __launch_bounds__(256)
void split_qkv(const float* __restrict__ Q, const float* __restrict__ K,
               const float* __restrict__ V)
{
    int idx = blockIdx.x * blockDim.x + threadIdx.x;   // 2,097,152 total
    int dk4 = idx & 31;
    int h   = (idx >> 5) & 15;
    int bs  = idx >> 9;                 // 0..4095
    int b   = bs >> 11, s = bs & 2047;
    size_t src = ((size_t)bs << 11) + h * 128 + (dk4 << 2);
    size_t dst = (((size_t)(b * 16 + h) << 11) + s) * 128 + (dk4 << 2);

    float4 q = *(const float4*)(g_Q + src);   (void)Q;
    q.x *= SCALE; q.y *= SCALE; q.z *= SCALE; q.w *= SCALE;
    float4 k = *(const float4*)(g_K + src);   (void)K;
    float4 v = *(const float4*)(g_V + src);   (void)V;

#define SPL(val, HI, LO) do { \
        __nv_bfloat16 _h0 = __float2bfloat16(val.x), _h1 = __float2bfloat16(val.y); \
        __nv_bfloat16 _h2 = __float2bfloat16(val.z), _h3 = __float2bfloat16(val.w); \
        __nv_bfloat16 _l0 = __float2bfloat16(val.x - __bfloat162float(_h0)); \
        __nv_bfloat16 _l1 = __float2bfloat16(val.y - __bfloat162float(_h1)); \
        __nv_bfloat16 _l2 = __float2bfloat16(val.z - __bfloat162float(_h2)); \
        __nv_bfloat16 _l3 = __float2bfloat16(val.w - __bfloat162float(_h3)); \
        ((__nv_bfloat162*)(HI + dst))[0] = __nv_bfloat162(_h0, _h1); \
        ((__nv_bfloat162*)(HI + dst))[1] = __nv_bfloat162(_h2, _h3); \
        ((__nv_bfloat162*)(LO + dst))[0] = __nv_bfloat162(_l0, _l1); \
        ((__nv_bfloat162*)(LO + dst))[1] = __nv_bfloat162(_l2, _l3); \
    } while (0)
    SPL(q, g_Qh, g_Ql);
    SPL(k, g_Kh, g_Kl);
    SPL(v, g_Vh, g_Vl);
#undef SPL
}

// ===========================================================================
// bf16 mma.sync GEMM (unchanged, validated round 4)
// ===========================================================================
#define STG_OP 10240u

__device__ __forceinline__
void gemm_mma_body(const __nv_bfloat16* __restrict__ A,
                   const __nv_bfloat16* __restrict__ B,
                   float* __restrict__ C)
{
    extern __shared__ __align__(128) char gsm[];
    const uint32_t sbase = smem_to_u32(gsm);
    const int tid = threadIdx.x;
    const int lane = tid & 31, wid = tid >> 5;
    const int bm = blockIdx.y * 128, bn = blockIdx.x * 128;
    const int wm = (wid >> 2) * 64, wn = (wid & 3) * 32;

    const __nv_bfloat16* Ag = A + (size_t)bm * KP;
    const __nv_bfloat16* Bg = B + (size_t)bn * KP;

    const uint32_t sA0 = sbase;
    const uint32_t sB0 = sbase + 4 * STG_OP;

    float c[4][4][4];
#pragma unroll
    for (int i = 0; i < 4; i++)
#pragma unroll
        for (int j = 0; j < 4; j++)
#pragma unroll
            for (int k = 0; k < 4; k++) c[i][j][k] = 0.f;

    const int frow0 = tid >> 2, fseg = tid & 3;
    const int frow1 = (tid + 256) >> 2;

#define GFILL(s) do {                                                         \
        int _buf = (s) & 3;                                                   \
        uint32_t _sa = sA0 + _buf * STG_OP;                                   \
        uint32_t _sb = sB0 + _buf * STG_OP;                                   \
        int _ks = (s) * 32;                                                   \
        uint32_t _d0 = (uint32_t)(frow0 * 80 + fseg * 16);                    \
        uint32_t _d1 = (uint32_t)(frow1 * 80 + fseg * 16);                    \
        const void* _ga0 = Ag + (size_t)frow0 * KP + _ks + fseg * 8;          \
        const void* _gb0 = Bg + (size_t)frow0 * KP + _ks + fseg * 8;          \
        const void* _ga1 = Ag + (size_t)frow1 * KP + _ks + fseg * 8;          \
        const void* _gb1 = Bg + (size_t)frow1 * KP + _ks + fseg * 8;          \
        cpa16(_sa + _d0, _ga0); cpa16(_sb + _d0, _gb0);                       \
        cpa16(_sa + _d1, _ga1); cpa16(_sb + _d1, _gb1);                       \
        asm volatile("cp.async.commit_group;" ::: "memory");                  \
    } while (0)

    GFILL(0); GFILL(1); GFILL(2);

    const uint32_t aRowOff = (uint32_t)((wm + (lane & 15)) * 80);
    const uint32_t bRowOff = (uint32_t)((wn + (lane & 7) + ((lane >> 4) << 3)) * 80);
    const uint32_t aColOff = (uint32_t)((lane >> 4) << 4);
    const uint32_t bColOff = (uint32_t)(((lane >> 3) & 1) << 4);

    for (int kt = 0; kt < KTILES; kt++) {
        asm volatile("cp.async.wait_group 2;" ::: "memory");
        __syncthreads();
        if (kt + 3 < KTILES) { GFILL(kt + 3); }
        else { asm volatile("cp.async.commit_group;" ::: "memory"); }

        const int buf = kt & 3;
        const uint32_t sa = sA0 + buf * STG_OP;
        const uint32_t sb = sB0 + buf * STG_OP;

#pragma unroll
        for (int ks = 0; ks < 2; ks++) {
            uint32_t a[4][4], bf[2][4];
            const uint32_t ac = ks * 32 + aColOff;
            const uint32_t bc = ks * 32 + bColOff;
#pragma unroll
            for (int mt = 0; mt < 4; mt++)
                LDSM4(a[mt], sa + aRowOff + (uint32_t)(mt * 16 * 80) + ac);
#pragma unroll
            for (int nt2 = 0; nt2 < 2; nt2++)
                LDSM4(bf[nt2], sb + bRowOff + (uint32_t)(nt2 * 16 * 80) + bc);
#pragma unroll
            for (int mt = 0; mt < 4; mt++)
#pragma unroll
                for (int nt = 0; nt < 4; nt++)
                    MMA16816(c[mt][nt], a[mt],
                             bf[nt >> 1][(nt & 1) * 2], bf[nt >> 1][(nt & 1) * 2 + 1]);
        }
    }
#undef GFILL

    const int r0 = bm + wm + (lane >> 2);
    const int c0 = bn + wn + (lane & 3) * 2;
#pragma unroll
    for (int mt = 0; mt < 4; mt++)
#pragma unroll
        for (int nt = 0; nt < 4; nt++) {
            int rr = r0 + mt * 16, cc = c0 + nt * 8;
            *(float2*)(C + (size_t)rr * Dm + cc)       = make_float2(c[mt][nt][0], c[mt][nt][1]);
            *(float2*)(C + (size_t)(rr + 8) * Dm + cc) = make_float2(c[mt][nt][2], c[mt][nt][3]);
        }
}

__global__ __launch_bounds__(256)
void gemm_bf3(const __nv_bfloat16* __restrict__ A, const __nv_bfloat16* __restrict__ B,
              float* __restrict__ C)
{
    gemm_mma_body(A, B, C);
}

__global__ __launch_bounds__(256)
void gemm_bf3_qkv(const __nv_bfloat16* __restrict__ A,
                  const __nv_bfloat16* __restrict__ WQ, const __nv_bfloat16* __restrict__ WK,
                  const __nv_bfloat16* __restrict__ WV,
                  float* __restrict__ Qo, float* __restrict__ Ko, float* __restrict__ Vo)
{
    const __nv_bfloat16* Bw = (blockIdx.z == 0) ? WQ : (blockIdx.z == 1) ? WK : WV;
    float*               C  = (blockIdx.z == 0) ? Qo : (blockIdx.z == 1) ? Ko : Vo;
    gemm_mma_body(A, Bw, C);
}

// ===========================================================================
// RoPE in-place on fp32 Q and K
// ===========================================================================
__global__ __launch_bounds__(256)
void rope_kernel(float* __restrict__ Qm, float* __restrict__ Km,
                 const int* __restrict__ pos)
{
    int idx = blockIdx.x * blockDim.x + threadIdx.x;
    int i = idx & 63;
    int h = (idx >> 6) & 15;
    int s = (idx >> 10) & (Sseq - 1);
    int b = idx >> 21;

    float ang = (float)pos[s] * g_invf[i];
    float sn, cs;
    sincosf(ang, &sn, &cs);

    size_t off = ((size_t)(b * Sseq + s)) * Dm + h * DKk + 2 * i;
    float2 q = *(float2*)(Qm + off);
    float2 k = *(float2*)(Km + off);
    *(float2*)(Qm + off) = make_float2(q.x * cs - q.y * sn, q.x * sn + q.y * cs);
    *(float2*)(Km + off) = make_float2(k.x * cs - k.y * sn, k.x * sn + k.y * cs);
}

// ===========================================================================
// Tensor-core flash attention, bf16-split, causal.
// BQ=BKV=64, 4 warps, warp owns 16 q-rows. FA2 register-fragment layout.
// smem (bf16, pitch 136 elems = 272 B): Qh,Ql,Kh,Kl,Vh,Vl tiles 64x128.
// ===========================================================================
#define FP 136
#define FPB 272
#define TILEB ((uint32_t)(64 * FPB))   // 17408 bytes

__global__ __launch_bounds__(128, 2)
void flash_bf16(const __nv_bfloat16* __restrict__ Qh, const __nv_bfloat16* __restrict__ Ql,
                const __nv_bfloat16* __restrict__ Kh, const __nv_bfloat16* __restrict__ Kl,
                const __nv_bfloat16* __restrict__ Vh, const __nv_bfloat16* __restrict__ Vl,
                float* __restrict__ O)
{
    extern __shared__ __align__(128) __nv_bfloat16 fsm[];
    const uint32_t sb = smem_to_u32(fsm);
    const uint32_t uQh = sb,            uQl = sb + TILEB;
    const uint32_t uKh = sb + 2*TILEB,  uKl = sb + 3*TILEB;
    const uint32_t uVh = sb + 4*TILEB,  uVl = sb + 5*TILEB;

    const int tid = threadIdx.x, lane = tid & 31, wid = tid >> 5;
    const int qt = (int)gridDim.x - 1 - (int)blockIdx.x;    // largest first
    const int bh = blockIdx.y;
    const int q0 = qt * 64;
    const size_t hbase = (size_t)bh * (2048 * 128);

    // Q tiles -> smem
#pragma unroll
    for (int i = 0; i < 8; i++) {
        int cc = tid + i * 128, row = cc >> 4, seg = cc & 15;
        uint32_t d = (uint32_t)(row * FPB + seg * 16);
        size_t g = hbase + (size_t)(q0 + row) * 128 + seg * 8;
        cpa16(uQh + d, Qh + g);
        cpa16(uQl + d, Ql + g);
    }
    asm volatile("cp.async.commit_group;" ::: "memory");

#define KVFILL(jj) do {                                                        \
        int _c0 = (jj) * 64;                                                   \
        _Pragma("unroll")                                                      \
        for (int _i = 0; _i < 8; _i++) {                                       \
            int _cc = tid + _i * 128, _row = _cc >> 4, _seg = _cc & 15;        \
            uint32_t _d = (uint32_t)(_row * FPB + _seg * 16);                  \
            size_t _g = hbase + (size_t)(_c0 + _row) * 128 + _seg * 8;         \
            cpa16(uKh + _d, Kh + _g); cpa16(uKl + _d, Kl + _g);                \
            cpa16(uVh + _d, Vh + _g); cpa16(uVl + _d, Vl + _g);                \
        }                                                                      \
        asm volatile("cp.async.commit_group;" ::: "memory");                   \
    } while (0)

    KVFILL(0);

    float co[16][4];
#pragma unroll
    for (int i = 0; i < 16; i++)
#pragma unroll
        for (int k = 0; k < 4; k++) co[i][k] = 0.f;
    float m0v = -1e30f, m1v = -1e30f, l0v = 0.f, l1v = 0.f;

    const uint32_t aoff  = (uint32_t)((wid * 16 + (lane & 15)) * FPB + ((lane >> 4) << 4));
    const uint32_t bKoff = (uint32_t)(((lane & 7) + ((lane >> 4) << 3)) * FPB + (((lane >> 3) & 1) << 4));
    const uint32_t vloff = (uint32_t)((lane & 15) * FPB + ((lane >> 4) << 4));

    for (int j = 0; j <= qt; j++) {
        asm volatile("cp.async.wait_group 0;" ::: "memory");
        __syncthreads();

        // ---- S = Q K^T (3 split passes fused) ----
        float cs[8][4];
#pragma unroll
        for (int i = 0; i < 8; i++)
#pragma unroll
            for (int k = 0; k < 4; k++) cs[i][k] = 0.f;

#pragma unroll
        for (int ks = 0; ks < 8; ks++) {
            uint32_t aH[4], aL[4];
            LDSM4(aH, uQh + aoff + ks * 32);
            LDSM4(aL, uQl + aoff + ks * 32);
#pragma unroll
            for (int np = 0; np < 4; np++) {
                uint32_t bH[4], bL[4];
                uint32_t bo = bKoff + (uint32_t)(np * 16 * FPB) + ks * 32;
                LDSM4(bH, uKh + bo);
                LDSM4(bL, uKl + bo);
                MMA16816(cs[2*np],   aH, bH[0], bH[1]);
                MMA16816(cs[2*np+1], aH, bH[2], bH[3]);
                MMA16816(cs[2*np],   aH, bL[0], bL[1]);
                MMA16816(cs[2*np+1], aH, bL[2], bL[3]);
                MMA16816(cs[2*np],   aL, bH[0], bH[1]);
                MMA16816(cs[2*np+1], aL, bH[2], bH[3]);
            }
        }

        // ---- causal mask on diagonal tile ----
        if (j == qt) {
            int g = lane >> 2, t2 = (lane & 3) * 2;
            int r0 = wid * 16 + g, r1 = r0 + 8;
#pragma unroll
            for (int nt = 0; nt < 8; nt++) {
                int cl = nt * 8 + t2;
                if (cl     > r0) cs[nt][0] = -1e30f;
                if (cl + 1 > r0) cs[nt][1] = -1e30f;
                if (cl     > r1) cs[nt][2] = -1e30f;
                if (cl + 1 > r1) cs[nt][3] = -1e30f;
            }
        }

        // ---- online softmax (rows owned by lane quads) ----
        float mx0 = -1e30f, mx1 = -1e30f;
#pragma unroll
        for (int nt = 0; nt < 8; nt++) {
            mx0 = fmaxf(mx0, fmaxf(cs[nt][0], cs[nt][1]));
            mx1 = fmaxf(mx1, fmaxf(cs[nt][2], cs[nt][3]));
        }
        mx0 = fmaxf(mx0, __shfl_xor_sync(0xffffffffu, mx0, 1));
        mx0 = fmaxf(mx0, __shfl_xor_sync(0xffffffffu, mx0, 2));
        mx1 = fmaxf(mx1, __shfl_xor_sync(0xffffffffu, mx1, 1));
        mx1 = fmaxf(mx1, __shfl_xor_sync(0xffffffffu, mx1, 2));
        float mn0 = fmaxf(m0v, mx0), mn1 = fmaxf(m1v, mx1);
        float al0 = __expf(m0v - mn0), al1 = __expf(m1v - mn1);
        m0v = mn0; m1v = mn1;
        float rs0 = 0.f, rs1 = 0.f;
#pragma unroll
        for (int nt = 0; nt < 8; nt++) {
            cs[nt][0] = __expf(cs[nt][0] - mn0);
            cs[nt][1] = __expf(cs[nt][1] - mn0);
            cs[nt][2] = __expf(cs[nt][2] - mn1);
            cs[nt][3] = __expf(cs[nt][3] - mn1);
            rs0 += cs[nt][0] + cs[nt][1];
            rs1 += cs[nt][2] + cs[nt][3];
        }
        rs0 += __shfl_xor_sync(0xffffffffu, rs0, 1);
        rs0 += __shfl_xor_sync(0xffffffffu, rs0, 2);
        rs1 += __shfl_xor_sync(0xffffffffu, rs1, 1);
        rs1 += __shfl_xor_sync(0xffffffffu, rs1, 2);
        l0v = l0v * al0 + rs0;
        l1v = l1v * al1 + rs1;
#pragma unroll
        for (int nt = 0; nt < 16; nt++) {
            co[nt][0] *= al0; co[nt][1] *= al0;
            co[nt][2] *= al1; co[nt][3] *= al1;
        }

        // ---- O += P V (3 split passes; P packed straight into A frags) ----
#pragma unroll
        for (int ks = 0; ks < 4; ks++) {
            float p0 = cs[2*ks][0],   p1 = cs[2*ks][1],   p2 = cs[2*ks][2],   p3 = cs[2*ks][3];
            float p4 = cs[2*ks+1][0], p5 = cs[2*ks+1][1], p6 = cs[2*ks+1][2], p7 = cs[2*ks+1][3];
            uint32_t aPh[4] = { pack_bf16x2(p0, p1), pack_bf16x2(p2, p3),
                                pack_bf16x2(p4, p5), pack_bf16x2(p6, p7) };
            uint32_t aPl[4] = {
                pack_bf16x2(p0 - bf16rt(p0), p1 - bf16rt(p1)),
                pack_bf16x2(p2 - bf16rt(p2), p3 - bf16rt(p3)),
                pack_bf16x2(p4 - bf16rt(p4), p5 - bf16rt(p5)),
                pack_bf16x2(p6 - bf16rt(p6), p7 - bf16rt(p7)) };
            uint32_t vb = vloff + (uint32_t)(ks * 16 * FPB);
#pragma unroll
            for (int dc = 0; dc < 8; dc++) {
                uint32_t vH[4], vL[4];
                LDSM4T(vH, uVh + vb + dc * 32);
                LDSM4T(vL, uVl + vb + dc * 32);
                MMA16816(co[2*dc],   aPh, vH[0], vH[1]);
                MMA16816(co[2*dc+1], aPh, vH[2], vH[3]);
                MMA16816(co[2*dc],   aPh, vL[0], vL[1]);
                MMA16816(co[2*dc+1], aPh, vL[2], vL[3]);
                MMA16816(co[2*dc],   aPl, vH[0], vH[1]);
                MMA16816(co[2*dc+1], aPl, vH[2], vH[3]);
            }
        }

        __syncthreads();
        if (j < qt) KVFILL(j + 1);
    }
#undef KVFILL

    // ---- epilogue ----
    float i0 = 1.f / l0v, i1 = 1.f / l1v;
    const size_t obase = ((size_t)(bh >> 4) * Sseq) * Dm + (bh & 15) * DKk;
    int g = lane >> 2, t2 = (lane & 3) * 2;
    int r0 = q0 + wid * 16 + g;
#pragma unroll
    for (int nt = 0; nt < 16; nt++) {
        *(float2*)(O + obase + (size_t)r0 * Dm + nt * 8 + t2) =
            make_float2(co[nt][0] * i0, co[nt][1] * i0);
        *(float2*)(O + obase + (size_t)(r0 + 8) * Dm + nt * 8 + t2) =
            make_float2(co[nt][2] * i1, co[nt][3] * i1);
    }
}

// ===========================================================================
extern "C" void kernel_launch(void* const* d_in, const int* in_sizes, int n_in,
                              void* d_out, int out_size)
{
    const float* x  = (const float*)d_in[0];
    const float* WQ = (const float*)d_in[1];
    const float* WK = (const float*)d_in[2];
    const float* WV = (const float*)d_in[3];
    const float* WO = (const float*)d_in[4];
    const int*  pos = (const int*)d_in[5];
    float* out = (float*)d_out;

    float *Qp, *Kp, *Vp, *AOp;
    __nv_bfloat16 *Axp, *Aaop, *Wqp, *Wkp, *Wvp, *Wop;
    __nv_bfloat16 *Qhp, *Qlp, *Khp, *Klp, *Vhp, *Vlp;
    cudaGetSymbolAddress((void**)&Qp,  g_Q);
    cudaGetSymbolAddress((void**)&Kp,  g_K);
    cudaGetSymbolAddress((void**)&Vp,  g_V);
    cudaGetSymbolAddress((void**)&AOp, g_AO);
    cudaGetSymbolAddress((void**)&Axp, g_Ax);
    cudaGetSymbolAddress((void**)&Aaop, g_Aao);
    cudaGetSymbolAddress((void**)&Wqp, g_Wq);
    cudaGetSymbolAddress((void**)&Wkp, g_Wk);
    cudaGetSymbolAddress((void**)&Wvp, g_Wv);
    cudaGetSymbolAddress((void**)&Wop, g_Wo);
    cudaGetSymbolAddress((void**)&Qhp, g_Qh);
    cudaGetSymbolAddress((void**)&Qlp, g_Ql);
    cudaGetSymbolAddress((void**)&Khp, g_Kh);
    cudaGetSymbolAddress((void**)&Klp, g_Kl);
    cudaGetSymbolAddress((void**)&Vhp, g_Vh);
    cudaGetSymbolAddress((void**)&Vlp, g_Vl);

    init_freqs<<<1, 64>>>();

    convert_split<<<(Mrows * Dm / 4) / 256, 256>>>(x,  Axp, 2048, 4096);
    convert_split<<<(Dm * Dm / 4) / 256, 256>>>(WQ, Wqp, 4096, 2048);
    convert_split<<<(Dm * Dm / 4) / 256, 256>>>(WK, Wkp, 4096, 2048);
    convert_split<<<(Dm * Dm / 4) / 256, 256>>>(WV, Wvp, 4096, 2048);
    convert_split<<<(Dm * Dm / 4) / 256, 256>>>(WO, Wop, 4096, 2048);

    cudaFuncSetAttribute(gemm_bf3_qkv, cudaFuncAttributeMaxDynamicSharedMemorySize, 81920);
    cudaFuncSetAttribute(gemm_bf3,     cudaFuncAttributeMaxDynamicSharedMemorySize, 81920);

    gemm_bf3_qkv<<<dim3(Dm / 128, Mrows / 128, 3), 256, 81920>>>(Axp, Wqp, Wkp, Wvp, Qp, Kp, Vp);

    rope_kernel<<<(Bb * Sseq * Hh * (DKk / 2)) / 256, 256>>>(Qp, Kp, pos);

    split_qkv<<<(Mrows * Dm / 4) / 256, 256>>>(Qp, Kp, Vp);

    cudaFuncSetAttribute(flash_bf16, cudaFuncAttributeMaxDynamicSharedMemorySize, 6 * 17408);
    flash_bf16<<<dim3(Sseq / 64, Bb * Hh), 128, 6 * 17408>>>(Qhp, Qlp, Khp, Klp, Vhp, Vlp, AOp);

    convert_split<<<(Mrows * Dm / 4) / 256, 256>>>(AOp, Aaop, 2048, 4096);
    gemm_bf3<<<dim3(Dm / 128, Mrows / 128), 256, 81920>>>(Aaop, Wop, out);
}

// round 6
// speedup vs baseline: 2.8319x; 1.0174x over previous
#include <cuda_runtime.h>
#include <cuda_bf16.h>
#include <math.h>
#include <cstdint>

#define Dm   2048
#define Bb   2
#define Sseq 2048
#define Hh   16
#define DKk  128
#define Mrows 4096
#define KP   6144          // 3 * 2048 (bf16x3 split packed along K)
#define KTILES (KP / 32)   // 192
#define SCALE 0.08838834764831844055f  // 1/sqrt(128)

__device__ float g_invf[64];

// bf16x3-split GEMM operands
__device__ __nv_bfloat16 g_Ax[(size_t)Mrows * KP];    // [hi|hi|lo]
__device__ __nv_bfloat16 g_Aao[(size_t)Mrows * KP];   // [hi|hi|lo]
__device__ __nv_bfloat16 g_Wq[(size_t)Dm * KP];       // [hi|lo|hi]
__device__ __nv_bfloat16 g_Wk[(size_t)Dm * KP];
__device__ __nv_bfloat16 g_Wv[(size_t)Dm * KP];
__device__ __nv_bfloat16 g_Wo[(size_t)Dm * KP];

// per-head split Q/K/V for flash:  [bh][s][128] bf16
#define HS ((size_t)32 * 2048 * 128)
__device__ __nv_bfloat16 g_Qh[HS];
__device__ __nv_bfloat16 g_Ql[HS];
__device__ __nv_bfloat16 g_Kh[HS];
__device__ __nv_bfloat16 g_Kl[HS];
__device__ __nv_bfloat16 g_Vh[HS];
__device__ __nv_bfloat16 g_Vl[HS];

__device__ __forceinline__ uint32_t smem_to_u32(const void* p) {
    uint32_t a;
    asm("{ .reg .u64 t; cvta.to.shared.u64 t, %1; cvt.u32.u64 %0, t; }"
        : "=r"(a) : "l"(p));
    return a;
}
__device__ __forceinline__ void cpa16(uint32_t d, const void* g) {
    asm volatile("cp.async.cg.shared.global [%0], [%1], 16;" :: "r"(d), "l"(g) : "memory");
}
__device__ __forceinline__ uint32_t pack_bf16x2(float lo, float hi) {
    uint32_t r;
    asm("cvt.rn.bf16x2.f32 %0, %1, %2;" : "=r"(r) : "f"(hi), "f"(lo));
    return r;
}
__device__ __forceinline__ float bf16rt(float x) {
    return __bfloat162float(__float2bfloat16(x));
}
// split pair (v0,v1) -> hi bf16x2, lo bf16x2
__device__ __forceinline__ void split_pair(float v0, float v1, uint32_t& hi, uint32_t& lo) {
    hi = pack_bf16x2(v0, v1);
    lo = pack_bf16x2(v0 - bf16rt(v0), v1 - bf16rt(v1));
}

#define LDSM4(R, addr) \
    asm volatile("ldmatrix.sync.aligned.m8n8.x4.shared.b16 {%0,%1,%2,%3}, [%4];" \
        : "=r"((R)[0]), "=r"((R)[1]), "=r"((R)[2]), "=r"((R)[3]) : "r"(addr))
#define LDSM4T(R, addr) \
    asm volatile("ldmatrix.sync.aligned.m8n8.x4.trans.shared.b16 {%0,%1,%2,%3}, [%4];" \
        : "=r"((R)[0]), "=r"((R)[1]), "=r"((R)[2]), "=r"((R)[3]) : "r"(addr))
#define MMA16816(C, A, B0, B1) \
    asm volatile("mma.sync.aligned.m16n8k16.row.col.f32.bf16.bf16.f32 " \
        "{%0,%1,%2,%3}, {%4,%5,%6,%7}, {%8,%9}, {%0,%1,%2,%3};" \
        : "+f"((C)[0]), "+f"((C)[1]), "+f"((C)[2]), "+f"((C)[3]) \
        : "r"((A)[0]), "r"((A)[1]), "r"((A)[2]), "r"((A)[3]), "r"(B0), "r"(B1))

// ===========================================================================
__global__ void init_freqs()
{
    int i = threadIdx.x;
    g_invf[i] = (float)pow(10000.0, -(double)i / 64.0);
}

// ===========================================================================
// fp32 [R,2048] -> bf16x3-packed [R,6144]
// ===========================================================================
__device__ __forceinline__
void conv_body(const float* __restrict__ X, __nv_bfloat16* __restrict__ Y,
               int hi2_off, int lo_off, int idx)
{
    int r  = idx >> 9;
    int c4 = idx & 511;
    float4 v = *(const float4*)(X + ((size_t)r << 11) + (c4 << 2));
    __nv_bfloat16 h0 = __float2bfloat16(v.x), h1 = __float2bfloat16(v.y);
    __nv_bfloat16 h2 = __float2bfloat16(v.z), h3 = __float2bfloat16(v.w);
    __nv_bfloat16 l0 = __float2bfloat16(v.x - __bfloat162float(h0));
    __nv_bfloat16 l1 = __float2bfloat16(v.y - __bfloat162float(h1));
    __nv_bfloat16 l2 = __float2bfloat16(v.z - __bfloat162float(h2));
    __nv_bfloat16 l3 = __float2bfloat16(v.w - __bfloat162float(h3));
    size_t row = (size_t)r * KP;
    __nv_bfloat162 hA = __nv_bfloat162(h0, h1), hB = __nv_bfloat162(h2, h3);
    __nv_bfloat162 lA = __nv_bfloat162(l0, l1), lB = __nv_bfloat162(l2, l3);
    __nv_bfloat162* p0 = (__nv_bfloat162*)(Y + row + (c4 << 2));
    __nv_bfloat162* p1 = (__nv_bfloat162*)(Y + row + hi2_off + (c4 << 2));
    __nv_bfloat162* p2 = (__nv_bfloat162*)(Y + row + lo_off + (c4 << 2));
    p0[0] = hA; p0[1] = hB;
    p1[0] = hA; p1[1] = hB;
    p2[0] = lA; p2[1] = lB;
}

__global__ __launch_bounds__(256)
void convert_x(const float* __restrict__ X, __nv_bfloat16* __restrict__ Y)
{
    conv_body(X, Y, 2048, 4096, blockIdx.x * blockDim.x + threadIdx.x);
}

// 4 weights in one launch (grid.z selects)
__global__ __launch_bounds__(256)
void convert_w4(const float* __restrict__ W0, const float* __restrict__ W1,
                const float* __restrict__ W2, const float* __restrict__ W3,
                __nv_bfloat16* __restrict__ Y0, __nv_bfloat16* __restrict__ Y1,
                __nv_bfloat16* __restrict__ Y2, __nv_bfloat16* __restrict__ Y3)
{
    const float* W = (blockIdx.z == 0) ? W0 : (blockIdx.z == 1) ? W1 :
                     (blockIdx.z == 2) ? W2 : W3;
    __nv_bfloat16* Y = (blockIdx.z == 0) ? Y0 : (blockIdx.z == 1) ? Y1 :
                       (blockIdx.z == 2) ? Y2 : Y3;
    conv_body(W, Y, 4096, 2048, blockIdx.x * blockDim.x + threadIdx.x);
}

// ===========================================================================
// Shared GEMM mainloop: accumulators c[4][4][4] for CTA 128x128, BK=32,
// 4-stage cp.async, 8 warps (2x4), warp 64x32. (validated round 4/5)
// ===========================================================================
#define STG_OP 10240u

__device__ __forceinline__
void gemm_mainloop(const __nv_bfloat16* __restrict__ A,
                   const __nv_bfloat16* __restrict__ B,
                   float c[4][4][4])
{
    extern __shared__ __align__(128) char gsm[];
    const uint32_t sbase = smem_to_u32(gsm);
    const int tid = threadIdx.x;
    const int lane = tid & 31, wid = tid >> 5;
    const int bm = blockIdx.y * 128, bn = blockIdx.x * 128;
    const int wm = (wid >> 2) * 64, wn = (wid & 3) * 32;

    const __nv_bfloat16* Ag = A + (size_t)bm * KP;
    const __nv_bfloat16* Bg = B + (size_t)bn * KP;

    const uint32_t sA0 = sbase;
    const uint32_t sB0 = sbase + 4 * STG_OP;

#pragma unroll
    for (int i = 0; i < 4; i++)
#pragma unroll
        for (int j = 0; j < 4; j++)
#pragma unroll
            for (int k = 0; k < 4; k++) c[i][j][k] = 0.f;

    const int frow0 = tid >> 2, fseg = tid & 3;
    const int frow1 = (tid + 256) >> 2;

#define GFILL(s) do {                                                         \
        int _buf = (s) & 3;                                                   \
        uint32_t _sa = sA0 + _buf * STG_OP;                                   \
        uint32_t _sb = sB0 + _buf * STG_OP;                                   \
        int _ks = (s) * 32;                                                   \
        uint32_t _d0 = (uint32_t)(frow0 * 80 + fseg * 16);                    \
        uint32_t _d1 = (uint32_t)(frow1 * 80 + fseg * 16);                    \
        const void* _ga0 = Ag + (size_t)frow0 * KP + _ks + fseg * 8;          \
        const void* _gb0 = Bg + (size_t)frow0 * KP + _ks + fseg * 8;          \
        const void* _ga1 = Ag + (size_t)frow1 * KP + _ks + fseg * 8;          \
        const void* _gb1 = Bg + (size_t)frow1 * KP + _ks + fseg * 8;          \
        cpa16(_sa + _d0, _ga0); cpa16(_sb + _d0, _gb0);                       \
        cpa16(_sa + _d1, _ga1); cpa16(_sb + _d1, _gb1);                       \
        asm volatile("cp.async.commit_group;" ::: "memory");                  \
    } while (0)

    GFILL(0); GFILL(1); GFILL(2);

    const uint32_t aRowOff = (uint32_t)((wm + (lane & 15)) * 80);
    const uint32_t bRowOff = (uint32_t)((wn + (lane & 7) + ((lane >> 4) << 3)) * 80);
    const uint32_t aColOff = (uint32_t)((lane >> 4) << 4);
    const uint32_t bColOff = (uint32_t)(((lane >> 3) & 1) << 4);

    for (int kt = 0; kt < KTILES; kt++) {
        asm volatile("cp.async.wait_group 2;" ::: "memory");
        __syncthreads();
        if (kt + 3 < KTILES) { GFILL(kt + 3); }
        else { asm volatile("cp.async.commit_group;" ::: "memory"); }

        const int buf = kt & 3;
        const uint32_t sa = sA0 + buf * STG_OP;
        const uint32_t sb = sB0 + buf * STG_OP;

#pragma unroll
        for (int ks = 0; ks < 2; ks++) {
            uint32_t a[4][4], bf[2][4];
            const uint32_t ac = ks * 32 + aColOff;
            const uint32_t bc = ks * 32 + bColOff;
#pragma unroll
            for (int mt = 0; mt < 4; mt++)
                LDSM4(a[mt], sa + aRowOff + (uint32_t)(mt * 16 * 80) + ac);
#pragma unroll
            for (int nt2 = 0; nt2 < 2; nt2++)
                LDSM4(bf[nt2], sb + bRowOff + (uint32_t)(nt2 * 16 * 80) + bc);
#pragma unroll
            for (int mt = 0; mt < 4; mt++)
#pragma unroll
                for (int nt = 0; nt < 4; nt++)
                    MMA16816(c[mt][nt], a[mt],
                             bf[nt >> 1][(nt & 1) * 2], bf[nt >> 1][(nt & 1) * 2 + 1]);
        }
    }
#undef GFILL
}

// ===========================================================================
// QKV GEMM with fused RoPE + scale + bf16-split epilogue.
// z=0: Q (rope+scale), z=1: K (rope), z=2: V (plain split).
// Fragment cols come in adjacent even pairs == RoPE pairs.
// ===========================================================================
__global__ __launch_bounds__(256)
void gemm_qkv_fused(const __nv_bfloat16* __restrict__ A,
                    const __nv_bfloat16* __restrict__ WQ, const __nv_bfloat16* __restrict__ WK,
                    const __nv_bfloat16* __restrict__ WV,
                    const int* __restrict__ pos)
{
    const int z = blockIdx.z;
    const __nv_bfloat16* Bw = (z == 0) ? WQ : (z == 1) ? WK : WV;

    float c[4][4][4];
    gemm_mainloop(A, Bw, c);

    __nv_bfloat16* HI = (z == 0) ? g_Qh : (z == 1) ? g_Kh : g_Vh;
    __nv_bfloat16* LO = (z == 0) ? g_Ql : (z == 1) ? g_Kl : g_Vl;

    const int lane = threadIdx.x & 31, wid = threadIdx.x >> 5;
    const int bm = blockIdx.y * 128, bn = blockIdx.x * 128;
    const int wm = (wid >> 2) * 64, wn = (wid & 3) * 32;
    const int r0 = bm + wm + (lane >> 2);
    const int c0 = bn + wn + (lane & 3) * 2;

#pragma unroll
    for (int mt = 0; mt < 4; mt++) {
#pragma unroll
        for (int half = 0; half < 2; half++) {
            const int rr = r0 + mt * 16 + half * 8;
            const int b = rr >> 11, s = rr & 2047;
            float sn = 0.f, cs = 1.f;
            const int p = pos[s];
#pragma unroll
            for (int nt = 0; nt < 4; nt++) {
                const int cc = c0 + nt * 8;
                const int h = cc >> 7, dk = cc & 127;
                float v0 = c[mt][nt][half * 2], v1 = c[mt][nt][half * 2 + 1];
                if (z < 2) {
                    const int i = dk >> 1;
                    float ang = (float)p * g_invf[i];
                    sincosf(ang, &sn, &cs);
                    float r1 = v0 * cs - v1 * sn;
                    float r2 = v0 * sn + v1 * cs;
                    v0 = r1; v1 = r2;
                    if (z == 0) { v0 *= SCALE; v1 *= SCALE; }
                }
                uint32_t hi, lo;
                split_pair(v0, v1, hi, lo);
                size_t dst = (((size_t)(b * 16 + h) << 11) + s) * 128 + dk;
                *(uint32_t*)(HI + dst) = hi;
                *(uint32_t*)(LO + dst) = lo;
            }
        }
    }
}

// ===========================================================================
// Final GEMM: out = AO' * WO'^T, plain fp32 epilogue
// ===========================================================================
__global__ __launch_bounds__(256)
void gemm_out(const __nv_bfloat16* __restrict__ A, const __nv_bfloat16* __restrict__ B,
              float* __restrict__ C)
{
    float c[4][4][4];
    gemm_mainloop(A, B, c);

    const int lane = threadIdx.x & 31, wid = threadIdx.x >> 5;
    const int bm = blockIdx.y * 128, bn = blockIdx.x * 128;
    const int wm = (wid >> 2) * 64, wn = (wid & 3) * 32;
    const int r0 = bm + wm + (lane >> 2);
    const int c0 = bn + wn + (lane & 3) * 2;
#pragma unroll
    for (int mt = 0; mt < 4; mt++)
#pragma unroll
        for (int nt = 0; nt < 4; nt++) {
            int rr = r0 + mt * 16, cc = c0 + nt * 8;
            *(float2*)(C + (size_t)rr * Dm + cc)       = make_float2(c[mt][nt][0], c[mt][nt][1]);
            *(float2*)(C + (size_t)(rr + 8) * Dm + cc) = make_float2(c[mt][nt][2], c[mt][nt][3]);
        }
}

// ===========================================================================
// Tensor-core flash attention, bf16-split, causal (validated round 5).
// Epilogue now writes AO' [hi|hi|lo] packed bf16 directly.
// ===========================================================================
#define FP 136
#define FPB 272
#define TILEB ((uint32_t)(64 * FPB))   // 17408 bytes

__global__ __launch_bounds__(128, 2)
void flash_bf16(const __nv_bfloat16* __restrict__ Qh, const __nv_bfloat16* __restrict__ Ql,
                const __nv_bfloat16* __restrict__ Kh, const __nv_bfloat16* __restrict__ Kl,
                const __nv_bfloat16* __restrict__ Vh, const __nv_bfloat16* __restrict__ Vl,
                __nv_bfloat16* __restrict__ AO)
{
    extern __shared__ __align__(128) __nv_bfloat16 fsm[];
    const uint32_t sb = smem_to_u32(fsm);
    const uint32_t uQh = sb,            uQl = sb + TILEB;
    const uint32_t uKh = sb + 2*TILEB,  uKl = sb + 3*TILEB;
    const uint32_t uVh = sb + 4*TILEB,  uVl = sb + 5*TILEB;

    const int tid = threadIdx.x, lane = tid & 31, wid = tid >> 5;
    const int qt = (int)gridDim.x - 1 - (int)blockIdx.x;
    const int bh = blockIdx.y;
    const int q0 = qt * 64;
    const size_t hbase = (size_t)bh * (2048 * 128);

#pragma unroll
    for (int i = 0; i < 8; i++) {
        int cc = tid + i * 128, row = cc >> 4, seg = cc & 15;
        uint32_t d = (uint32_t)(row * FPB + seg * 16);
        size_t g = hbase + (size_t)(q0 + row) * 128 + seg * 8;
        cpa16(uQh + d, Qh + g);
        cpa16(uQl + d, Ql + g);
    }
    asm volatile("cp.async.commit_group;" ::: "memory");

#define KVFILL(jj) do {                                                        \
        int _c0 = (jj) * 64;                                                   \
        _Pragma("unroll")                                                      \
        for (int _i = 0; _i < 8; _i++) {                                       \
            int _cc = tid + _i * 128, _row = _cc >> 4, _seg = _cc & 15;        \
            uint32_t _d = (uint32_t)(_row * FPB + _seg * 16);                  \
            size_t _g = hbase + (size_t)(_c0 + _row) * 128 + _seg * 8;         \
            cpa16(uKh + _d, Kh + _g); cpa16(uKl + _d, Kl + _g);                \
            cpa16(uVh + _d, Vh + _g); cpa16(uVl + _d, Vl + _g);                \
        }                                                                      \
        asm volatile("cp.async.commit_group;" ::: "memory");                   \
    } while (0)

    KVFILL(0);

    float co[16][4];
#pragma unroll
    for (int i = 0; i < 16; i++)
#pragma unroll
        for (int k = 0; k < 4; k++) co[i][k] = 0.f;
    float m0v = -1e30f, m1v = -1e30f, l0v = 0.f, l1v = 0.f;

    const uint32_t aoff  = (uint32_t)((wid * 16 + (lane & 15)) * FPB + ((lane >> 4) << 4));
    const uint32_t bKoff = (uint32_t)(((lane & 7) + ((lane >> 4) << 3)) * FPB + (((lane >> 3) & 1) << 4));
    const uint32_t vloff = (uint32_t)((lane & 15) * FPB + ((lane >> 4) << 4));

    for (int j = 0; j <= qt; j++) {
        asm volatile("cp.async.wait_group 0;" ::: "memory");
        __syncthreads();

        float cs[8][4];
#pragma unroll
        for (int i = 0; i < 8; i++)
#pragma unroll
            for (int k = 0; k < 4; k++) cs[i][k] = 0.f;

#pragma unroll
        for (int ks = 0; ks < 8; ks++) {
            uint32_t aH[4], aL[4];
            LDSM4(aH, uQh + aoff + ks * 32);
            LDSM4(aL, uQl + aoff + ks * 32);
#pragma unroll
            for (int np = 0; np < 4; np++) {
                uint32_t bH[4], bL[4];
                uint32_t bo = bKoff + (uint32_t)(np * 16 * FPB) + ks * 32;
                LDSM4(bH, uKh + bo);
                LDSM4(bL, uKl + bo);
                MMA16816(cs[2*np],   aH, bH[0], bH[1]);
                MMA16816(cs[2*np+1], aH, bH[2], bH[3]);
                MMA16816(cs[2*np],   aH, bL[0], bL[1]);
                MMA16816(cs[2*np+1], aH, bL[2], bL[3]);
                MMA16816(cs[2*np],   aL, bH[0], bH[1]);
                MMA16816(cs[2*np+1], aL, bH[2], bH[3]);
            }
        }

        if (j == qt) {
            int g = lane >> 2, t2 = (lane & 3) * 2;
            int r0 = wid * 16 + g, r1 = r0 + 8;
#pragma unroll
            for (int nt = 0; nt < 8; nt++) {
                int cl = nt * 8 + t2;
                if (cl     > r0) cs[nt][0] = -1e30f;
                if (cl + 1 > r0) cs[nt][1] = -1e30f;
                if (cl     > r1) cs[nt][2] = -1e30f;
                if (cl + 1 > r1) cs[nt][3] = -1e30f;
            }
        }

        float mx0 = -1e30f, mx1 = -1e30f;
#pragma unroll
        for (int nt = 0; nt < 8; nt++) {
            mx0 = fmaxf(mx0, fmaxf(cs[nt][0], cs[nt][1]));
            mx1 = fmaxf(mx1, fmaxf(cs[nt][2], cs[nt][3]));
        }
        mx0 = fmaxf(mx0, __shfl_xor_sync(0xffffffffu, mx0, 1));
        mx0 = fmaxf(mx0, __shfl_xor_sync(0xffffffffu, mx0, 2));
        mx1 = fmaxf(mx1, __shfl_xor_sync(0xffffffffu, mx1, 1));
        mx1 = fmaxf(mx1, __shfl_xor_sync(0xffffffffu, mx1, 2));
        float mn0 = fmaxf(m0v, mx0), mn1 = fmaxf(m1v, mx1);
        float al0 = __expf(m0v - mn0), al1 = __expf(m1v - mn1);
        m0v = mn0; m1v = mn1;
        float rs0 = 0.f, rs1 = 0.f;
#pragma unroll
        for (int nt = 0; nt < 8; nt++) {
            cs[nt][0] = __expf(cs[nt][0] - mn0);
            cs[nt][1] = __expf(cs[nt][1] - mn0);
            cs[nt][2] = __expf(cs[nt][2] - mn1);
            cs[nt][3] = __expf(cs[nt][3] - mn1);
            rs0 += cs[nt][0] + cs[nt][1];
            rs1 += cs[nt][2] + cs[nt][3];
        }
        rs0 += __shfl_xor_sync(0xffffffffu, rs0, 1);
        rs0 += __shfl_xor_sync(0xffffffffu, rs0, 2);
        rs1 += __shfl_xor_sync(0xffffffffu, rs1, 1);
        rs1 += __shfl_xor_sync(0xffffffffu, rs1, 2);
        l0v = l0v * al0 + rs0;
        l1v = l1v * al1 + rs1;
#pragma unroll
        for (int nt = 0; nt < 16; nt++) {
            co[nt][0] *= al0; co[nt][1] *= al0;
            co[nt][2] *= al1; co[nt][3] *= al1;
        }

#pragma unroll
        for (int ks = 0; ks < 4; ks++) {
            float p0 = cs[2*ks][0],   p1 = cs[2*ks][1],   p2 = cs[2*ks][2],   p3 = cs[2*ks][3];
            float p4 = cs[2*ks+1][0], p5 = cs[2*ks+1][1], p6 = cs[2*ks+1][2], p7 = cs[2*ks+1][3];
            uint32_t aPh[4] = { pack_bf16x2(p0, p1), pack_bf16x2(p2, p3),
                                pack_bf16x2(p4, p5), pack_bf16x2(p6, p7) };
            uint32_t aPl[4] = {
                pack_bf16x2(p0 - bf16rt(p0), p1 - bf16rt(p1)),
                pack_bf16x2(p2 - bf16rt(p2), p3 - bf16rt(p3)),
                pack_bf16x2(p4 - bf16rt(p4), p5 - bf16rt(p5)),
                pack_bf16x2(p6 - bf16rt(p6), p7 - bf16rt(p7)) };
            uint32_t vb = vloff + (uint32_t)(ks * 16 * FPB);
#pragma unroll
            for (int dc = 0; dc < 8; dc++) {
                uint32_t vH[4], vL[4];
                LDSM4T(vH, uVh + vb + dc * 32);
                LDSM4T(vL, uVl + vb + dc * 32);
                MMA16816(co[2*dc],   aPh, vH[0], vH[1]);
                MMA16816(co[2*dc+1], aPh, vH[2], vH[3]);
                MMA16816(co[2*dc],   aPh, vL[0], vL[1]);
                MMA16816(co[2*dc+1], aPh, vL[2], vL[3]);
                MMA16816(co[2*dc],   aPl, vH[0], vH[1]);
                MMA16816(co[2*dc+1], aPl, vH[2], vH[3]);
            }
        }

        __syncthreads();
        if (j < qt) KVFILL(j + 1);
    }
#undef KVFILL

    // ---- epilogue: write AO' packed [hi|hi|lo] bf16 directly ----
    float i0 = 1.f / l0v, i1 = 1.f / l1v;
    const int b = bh >> 4, h = bh & 15;
    int g = lane >> 2, t2 = (lane & 3) * 2;
    const int r0 = b * 2048 + q0 + wid * 16 + g;
    const int cbase = h * 128 + t2;
#pragma unroll
    for (int nt = 0; nt < 16; nt++) {
        const int cc = cbase + nt * 8;
        uint32_t hi0, lo0, hi1, lo1;
        split_pair(co[nt][0] * i0, co[nt][1] * i0, hi0, lo0);
        split_pair(co[nt][2] * i1, co[nt][3] * i1, hi1, lo1);
        __nv_bfloat16* row0 = AO + (size_t)r0 * KP + cc;
        __nv_bfloat16* row1 = AO + (size_t)(r0 + 8) * KP + cc;
        *(uint32_t*)(row0)        = hi0;
        *(uint32_t*)(row0 + 2048) = hi0;
        *(uint32_t*)(row0 + 4096) = lo0;
        *(uint32_t*)(row1)        = hi1;
        *(uint32_t*)(row1 + 2048) = hi1;
        *(uint32_t*)(row1 + 4096) = lo1;
    }
}

// ===========================================================================
extern "C" void kernel_launch(void* const* d_in, const int* in_sizes, int n_in,
                              void* d_out, int out_size)
{
    const float* x  = (const float*)d_in[0];
    const float* WQ = (const float*)d_in[1];
    const float* WK = (const float*)d_in[2];
    const float* WV = (const float*)d_in[3];
    const float* WO = (const float*)d_in[4];
    const int*  pos = (const int*)d_in[5];
    float* out = (float*)d_out;

    __nv_bfloat16 *Axp, *Aaop, *Wqp, *Wkp, *Wvp, *Wop;
    __nv_bfloat16 *Qhp, *Qlp, *Khp, *Klp, *Vhp, *Vlp;
    cudaGetSymbolAddress((void**)&Axp, g_Ax);
    cudaGetSymbolAddress((void**)&Aaop, g_Aao);
    cudaGetSymbolAddress((void**)&Wqp, g_Wq);
    cudaGetSymbolAddress((void**)&Wkp, g_Wk);
    cudaGetSymbolAddress((void**)&Wvp, g_Wv);
    cudaGetSymbolAddress((void**)&Wop, g_Wo);
    cudaGetSymbolAddress((void**)&Qhp, g_Qh);
    cudaGetSymbolAddress((void**)&Qlp, g_Ql);
    cudaGetSymbolAddress((void**)&Khp, g_Kh);
    cudaGetSymbolAddress((void**)&Klp, g_Kl);
    cudaGetSymbolAddress((void**)&Vhp, g_Vh);
    cudaGetSymbolAddress((void**)&Vlp, g_Vl);

    init_freqs<<<1, 64>>>();

    convert_x<<<(Mrows * Dm / 4) / 256, 256>>>(x, Axp);
    convert_w4<<<dim3((Dm * Dm / 4) / 256, 1, 4), 256>>>(WQ, WK, WV, WO, Wqp, Wkp, Wvp, Wop);

    cudaFuncSetAttribute(gemm_qkv_fused, cudaFuncAttributeMaxDynamicSharedMemorySize, 81920);
    cudaFuncSetAttribute(gemm_out,       cudaFuncAttributeMaxDynamicSharedMemorySize, 81920);

    gemm_qkv_fused<<<dim3(Dm / 128, Mrows / 128, 3), 256, 81920>>>(Axp, Wqp, Wkp, Wvp, pos);

    cudaFuncSetAttribute(flash_bf16, cudaFuncAttributeMaxDynamicSharedMemorySize, 6 * 17408);
    flash_bf16<<<dim3(Sseq / 64, Bb * Hh), 128, 6 * 17408>>>(Qhp, Qlp, Khp, Klp, Vhp, Vlp, Aaop);

    gemm_out<<<dim3(Dm / 128, Mrows / 128), 256, 81920>>>(Aaop, Wop, out);
}